// round 1
// baseline (speedup 1.0000x reference)
#include <cuda_runtime.h>

#define NN 100000
#define EE 1600000
#define ET (EE + NN)   // edges + self loops

// ---------------- scratch (device globals; no allocation allowed) ------------
__device__ float g_h  [(size_t)NN * 64];    // GAT h = x3 @ gat_w
__device__ float g_x3 [(size_t)NN * 64];    // aggregated GAT output (pre-bias; bias folded)
__device__ float g_h1 [(size_t)NN * 384];   // fc1 activation
__device__ float g_h2 [(size_t)NN * 128];   // fc2 activation
__device__ float g_as [NN];
__device__ float g_ad [NN];
__device__ float g_denom[NN];
__device__ float g_ex [ET];
__device__ float g_u1[384], g_u2[384], g_cc[384];
__device__ int   g_is64;

// ---------------- int32/int64 edge-index detection ---------------------------
// If the buffer is int64 little-endian, every odd 32-bit word (high half) is 0
// (indices < 2^31). With int32 data those words are random indices in [0,1e5):
// probability all 256 sampled are zero is ~0.
__global__ void detect_kernel(const unsigned* __restrict__ p) {
    __shared__ unsigned sh[256];
    sh[threadIdx.x] = p[2 * threadIdx.x + 1];
    __syncthreads();
    if (threadIdx.x == 0) {
        unsigned o = 0;
        for (int i = 0; i < 256; i++) o |= sh[i];
        g_is64 = (o == 0) ? 1 : 0;
    }
}

// ---------------- precompute rank-2 epilogue vectors for fc1 -----------------
// u1[k] = sum_j w1[j]  * fc1_w[j,k]
// u2[k] = sum_j w2[j]  * fc1_w[64+j,k]
// cc[k] = fc1_b[k] + sum_j b1[j]*fc1_w[j,k] + b2[j]*fc1_w[64+j,k] + gat_b[j]*fc1_w[128+j,k]
__global__ void prep_kernel(const float* __restrict__ w1, const float* __restrict__ b1,
                            const float* __restrict__ w2, const float* __restrict__ b2,
                            const float* __restrict__ gatb,
                            const float* __restrict__ fc1w, const float* __restrict__ fc1b) {
    int k = threadIdx.x;  // 384 threads
    float s1 = 0.f, s2 = 0.f, c = fc1b[k];
    for (int j = 0; j < 64; j++) {
        float wa = fc1w[(size_t)j * 384 + k];
        float wb = fc1w[(size_t)(64 + j) * 384 + k];
        float wc = fc1w[(size_t)(128 + j) * 384 + k];
        s1 += w1[j] * wa;
        s2 += w2[j] * wb;
        c  += b1[j] * wa + b2[j] * wb + gatb[j] * wc;
    }
    g_u1[k] = s1; g_u2[k] = s2; g_cc[k] = c;
}

// ---------------- zero accumulators ------------------------------------------
__global__ void zero_kernel() {
    size_t stride = (size_t)gridDim.x * blockDim.x;
    size_t i0 = (size_t)blockIdx.x * blockDim.x + threadIdx.x;
    for (size_t p = i0; p < (size_t)NN * 64; p += stride) g_x3[p] = 0.f;
    for (size_t p = i0; p < (size_t)NN; p += stride) g_denom[p] = 0.f;
}

// ---------------- alpha_src / alpha_dst per node (warp per node) -------------
__global__ void alpha_kernel(const float* __restrict__ asrc, const float* __restrict__ adst) {
    int gw = (int)((blockIdx.x * blockDim.x + threadIdx.x) >> 5);
    int lane = threadIdx.x & 31;
    if (gw >= NN) return;
    float h0 = g_h[(size_t)gw * 64 + lane];
    float h1 = g_h[(size_t)gw * 64 + 32 + lane];
    float s = h0 * asrc[lane] + h1 * asrc[32 + lane];
    float d = h0 * adst[lane] + h1 * adst[32 + lane];
#pragma unroll
    for (int o = 16; o; o >>= 1) {
        s += __shfl_xor_sync(0xffffffffu, s, o);
        d += __shfl_xor_sync(0xffffffffu, d, o);
    }
    if (lane == 0) { g_as[gw] = s; g_ad[gw] = d; }
}

__device__ __forceinline__ void load_edge(const void* idx, int e, int is64, int& s, int& d) {
    if (e < EE) {
        if (is64) {
            const long long* q = (const long long*)idx;
            s = (int)q[e]; d = (int)q[EE + e];
        } else {
            const int* q = (const int*)idx;
            s = q[e]; d = q[EE + e];
        }
    } else {
        s = d = e - EE;  // self loop
    }
}

// ---------------- edge pass A: ex = exp(leakyrelu(as+ad)); denom += ex -------
__global__ void edge_a_kernel(const void* __restrict__ idx) {
    int e = blockIdx.x * blockDim.x + threadIdx.x;
    if (e >= ET) return;
    int is64 = g_is64;
    int s, d;
    load_edge(idx, e, is64, s, d);
    float v = g_as[s] + g_ad[d];
    v = (v > 0.f) ? v : 0.2f * v;
    float ex = expf(v);
    g_ex[e] = ex;
    atomicAdd(&g_denom[d], ex);
}

// ---------------- edge pass B: x3[d] += (ex/denom[d]) * h[s] (warp per edge) -
__global__ void edge_b_kernel(const void* __restrict__ idx) {
    int e = (int)((blockIdx.x * (size_t)blockDim.x + threadIdx.x) >> 5);
    int lane = threadIdx.x & 31;
    if (e >= ET) return;
    int is64 = g_is64;
    int s, d;
    load_edge(idx, e, is64, s, d);
    float coeff = g_ex[e] / (g_denom[d] + 1e-16f);
    float2 hv = *(const float2*)(g_h + (size_t)s * 64 + lane * 2);
    atomicAdd(&g_x3[(size_t)d * 64 + lane * 2], coeff * hv.x);
    atomicAdd(&g_x3[(size_t)d * 64 + lane * 2 + 1], coeff * hv.y);
}

// ---------------- generic fp32 GEMM: C[n,Ncols] = op(A[n,K] @ W[K,:]) --------
// 64x64 block tile, 256 threads, 4x4 microtile, BK=16. K must be mult of 16.
// Epilogue: optional bias, optional rank-2 (xr ? x0*u1[c]+x1*u2[c]+cc[c]), relu.
__global__ void gemm_kernel(const float* __restrict__ A, int lda, int acol,
                            const float* __restrict__ W, int ldw, int wrow0,
                            const float* __restrict__ bias,
                            float* __restrict__ C, int ldc,
                            int n, int K, int do_relu,
                            const float* __restrict__ xr,
                            const float* __restrict__ u1,
                            const float* __restrict__ u2,
                            const float* __restrict__ cc) {
    __shared__ float As[16][68];   // [k][row]
    __shared__ float Ws[16][68];   // [k][col]
    int tid = threadIdx.x;
    int tx = tid & 15, ty = tid >> 4;
    int row0 = blockIdx.x * 64;
    int col0 = blockIdx.y * 64;
    float acc[4][4] = {};

    for (int kk = 0; kk < K; kk += 16) {
#pragma unroll
        for (int l = 0; l < 4; l++) {
            int li = tid + l * 256;
            int r = li >> 4, c = li & 15;
            int gr = row0 + r;
            As[c][r] = (gr < n) ? A[(size_t)gr * lda + acol + kk + c] : 0.f;
        }
#pragma unroll
        for (int l = 0; l < 4; l++) {
            int li = tid + l * 256;
            int r = li >> 6, c = li & 63;
            Ws[r][c] = W[(size_t)(wrow0 + kk + r) * ldw + col0 + c];
        }
        __syncthreads();
#pragma unroll
        for (int k = 0; k < 16; k++) {
            float4 a = *(const float4*)&As[k][ty * 4];
            float4 b = *(const float4*)&Ws[k][tx * 4];
            float av[4] = {a.x, a.y, a.z, a.w};
            float bv[4] = {b.x, b.y, b.z, b.w};
#pragma unroll
            for (int i = 0; i < 4; i++)
#pragma unroll
                for (int j = 0; j < 4; j++)
                    acc[i][j] += av[i] * bv[j];
        }
        __syncthreads();
    }

#pragma unroll
    for (int i = 0; i < 4; i++) {
        int r = row0 + ty * 4 + i;
        if (r >= n) continue;
        float xa = 0.f, xb = 0.f;
        if (xr) { xa = xr[(size_t)r * 130]; xb = xr[(size_t)r * 130 + 1]; }
#pragma unroll
        for (int j = 0; j < 4; j++) {
            int c = col0 + tx * 4 + j;
            float v = acc[i][j];
            if (bias) v += bias[c];
            if (xr)   v += xa * u1[c] + xb * u2[c] + cc[c];
            if (do_relu) v = fmaxf(v, 0.f);
            C[(size_t)r * ldc + c] = v;
        }
    }
}

// -----------------------------------------------------------------------------
extern "C" void kernel_launch(void* const* d_in, const int* in_sizes, int n_in,
                              void* d_out, int out_size) {
    const float* x    = (const float*)d_in[0];
    const void*  ei   = d_in[1];
    const float* w1   = (const float*)d_in[2];
    const float* b1   = (const float*)d_in[3];
    const float* w2   = (const float*)d_in[4];
    const float* b2   = (const float*)d_in[5];
    const float* gatw = (const float*)d_in[6];
    const float* asrc = (const float*)d_in[7];
    const float* adst = (const float*)d_in[8];
    const float* gatb = (const float*)d_in[9];
    const float* fc1w = (const float*)d_in[10];
    const float* fc1b = (const float*)d_in[11];
    const float* fc2w = (const float*)d_in[12];
    const float* fc2b = (const float*)d_in[13];
    const float* fc3w = (const float*)d_in[14];
    const float* fc3b = (const float*)d_in[15];
    float* out = (float*)d_out;

    void *ph, *px3, *ph1, *ph2, *pu1, *pu2, *pcc;
    cudaGetSymbolAddress(&ph,  g_h);
    cudaGetSymbolAddress(&px3, g_x3);
    cudaGetSymbolAddress(&ph1, g_h1);
    cudaGetSymbolAddress(&ph2, g_h2);
    cudaGetSymbolAddress(&pu1, g_u1);
    cudaGetSymbolAddress(&pu2, g_u2);
    cudaGetSymbolAddress(&pcc, g_cc);

    const int GX = (NN + 63) / 64;  // 1563

    detect_kernel<<<1, 256>>>((const unsigned*)ei);
    prep_kernel<<<1, 384>>>(w1, b1, w2, b2, gatb, fc1w, fc1b);
    zero_kernel<<<2048, 256>>>();

    // h = x[:,2:130] @ gat_w        (K=128, 64 cols)
    gemm_kernel<<<dim3(GX, 1), 256>>>(x, 130, 2, gatw, 64, 0, nullptr,
                                      (float*)ph, 64, NN, 128, 0,
                                      nullptr, nullptr, nullptr, nullptr);
    // per-node attention logits
    alpha_kernel<<<(NN + 7) / 8, 256>>>(asrc, adst);
    // edge softmax (max-free; numerically safe here) + aggregation
    edge_a_kernel<<<(ET + 255) / 256, 256>>>(ei);
    edge_b_kernel<<<(ET + 7) / 8, 256>>>(ei);

    // fc1: relu( x3 @ fc1_w[128:192,:] + x0*u1 + x1*u2 + cc )   (K=64, 384 cols)
    gemm_kernel<<<dim3(GX, 6), 256>>>((const float*)px3, 64, 0, fc1w, 384, 128, nullptr,
                                      (float*)ph1, 384, NN, 64, 1,
                                      x, (const float*)pu1, (const float*)pu2, (const float*)pcc);
    // fc2: relu( h1 @ fc2_w + fc2_b )                            (K=384, 128 cols)
    gemm_kernel<<<dim3(GX, 2), 256>>>((const float*)ph1, 384, 0, fc2w, 128, 0, fc2b,
                                      (float*)ph2, 128, NN, 384, 1,
                                      nullptr, nullptr, nullptr, nullptr);
    // fc3: h2 @ fc3_w + fc3_b                                    (K=128, 64 cols)
    gemm_kernel<<<dim3(GX, 1), 256>>>((const float*)ph2, 128, 0, fc3w, 64, 0, fc3b,
                                      out, 64, NN, 128, 0,
                                      nullptr, nullptr, nullptr, nullptr);
}

// round 2
// speedup vs baseline: 1.1998x; 1.1998x over previous
#include <cuda_runtime.h>
#include <math.h>

#define NN 100000
#define EE 1600000
#define NSB ((NN + 511) / 512)   // 196 scan blocks

// ---------------- scratch (device globals; no allocation allowed) ------------
__device__ float g_h  [(size_t)NN * 64];    // GAT h = x[:,2:] @ gat_w
__device__ float g_x3 [(size_t)NN * 64];    // aggregated GAT output (pre-bias)
__device__ float g_h1 [(size_t)NN * 384];   // fc1 activation
__device__ float g_h2 [(size_t)NN * 128];   // fc2 activation
__device__ float g_as [NN];
__device__ float g_ad [NN];
__device__ int   g_cnt[NN];                 // in-degree
__device__ int   g_off[NN];                 // CSR row offsets (exclusive scan)
__device__ int   g_pos[NN];                 // scatter cursors
__device__ int   g_srcs[EE];                // CSR src indices
__device__ float g_exs [EE];                // per-edge exp(leakyrelu(...))
__device__ int   g_bsum[NSB], g_boff[NSB];
__device__ float g_u1[384], g_u2[384], g_cc[384];
__device__ int   g_is64;

// ---------------- int32/int64 edge-index detection ---------------------------
__global__ void detect_kernel(const unsigned* __restrict__ p) {
    __shared__ unsigned sh[256];
    sh[threadIdx.x] = p[2 * threadIdx.x + 1];
    __syncthreads();
    if (threadIdx.x == 0) {
        unsigned o = 0;
        for (int i = 0; i < 256; i++) o |= sh[i];
        g_is64 = (o == 0) ? 1 : 0;
    }
}

// ---------------- precompute rank-2 epilogue vectors for fc1 -----------------
__global__ void prep_kernel(const float* __restrict__ w1, const float* __restrict__ b1,
                            const float* __restrict__ w2, const float* __restrict__ b2,
                            const float* __restrict__ gatb,
                            const float* __restrict__ fc1w, const float* __restrict__ fc1b) {
    int k = threadIdx.x;  // 384 threads
    float s1 = 0.f, s2 = 0.f, c = fc1b[k];
    for (int j = 0; j < 64; j++) {
        float wa = fc1w[(size_t)j * 384 + k];
        float wb = fc1w[(size_t)(64 + j) * 384 + k];
        float wc = fc1w[(size_t)(128 + j) * 384 + k];
        s1 += w1[j] * wa;
        s2 += w2[j] * wb;
        c  += b1[j] * wa + b2[j] * wb + gatb[j] * wc;
    }
    g_u1[k] = s1; g_u2[k] = s2; g_cc[k] = c;
}

__global__ void zero_cnt_kernel() {
    int i = blockIdx.x * blockDim.x + threadIdx.x;
    if (i < NN) g_cnt[i] = 0;
}

// ---------------- degree histogram -------------------------------------------
__global__ void hist_kernel(const void* __restrict__ idx) {
    int e = blockIdx.x * blockDim.x + threadIdx.x;
    if (e >= EE) return;
    int d = g_is64 ? (int)((const long long*)idx)[EE + e]
                   : ((const int*)idx)[EE + e];
    atomicAdd(&g_cnt[d], 1);
}

// ---------------- 3-kernel exclusive scan over g_cnt -------------------------
__global__ void scan1_kernel() {               // grid NSB, 256 thr
    __shared__ int sh[256];
    int b = blockIdx.x, t = threadIdx.x;
    int i0 = b * 512 + t;
    int v = 0;
    if (i0 < NN) v += g_cnt[i0];
    if (i0 + 256 < NN) v += g_cnt[i0 + 256];
    sh[t] = v; __syncthreads();
    for (int o = 128; o; o >>= 1) { if (t < o) sh[t] += sh[t + o]; __syncthreads(); }
    if (t == 0) g_bsum[b] = sh[0];
}

__global__ void scan2_kernel() {               // 1 block, 256 thr (NSB <= 256)
    __shared__ int sh[256];
    int t = threadIdx.x;
    int v = (t < NSB) ? g_bsum[t] : 0;
    sh[t] = v;
    for (int o = 1; o < 256; o <<= 1) {
        __syncthreads();
        int u = (t >= o) ? sh[t - o] : 0;
        __syncthreads();
        sh[t] += u;
    }
    __syncthreads();
    if (t < NSB) g_boff[t] = sh[t] - v;        // exclusive
}

__global__ void scan3_kernel() {               // grid NSB, 512 thr
    __shared__ int sh[512];
    int b = blockIdx.x, t = threadIdx.x;
    int i = b * 512 + t;
    int c = (i < NN) ? g_cnt[i] : 0;
    sh[t] = c;
    for (int o = 1; o < 512; o <<= 1) {
        __syncthreads();
        int u = (t >= o) ? sh[t - o] : 0;
        __syncthreads();
        sh[t] += u;
    }
    __syncthreads();
    if (i < NN) {
        int excl = sh[t] - c + g_boff[b];
        g_off[i] = excl;
        g_pos[i] = excl;
    }
}

// ---------------- alpha_src / alpha_dst per node (warp per node) -------------
__global__ void alpha_kernel(const float* __restrict__ asrc, const float* __restrict__ adst) {
    int gw = (int)((blockIdx.x * blockDim.x + threadIdx.x) >> 5);
    int lane = threadIdx.x & 31;
    if (gw >= NN) return;
    float h0 = g_h[(size_t)gw * 64 + lane];
    float h1 = g_h[(size_t)gw * 64 + 32 + lane];
    float s = h0 * asrc[lane] + h1 * asrc[32 + lane];
    float d = h0 * adst[lane] + h1 * adst[32 + lane];
#pragma unroll
    for (int o = 16; o; o >>= 1) {
        s += __shfl_xor_sync(0xffffffffu, s, o);
        d += __shfl_xor_sync(0xffffffffu, d, o);
    }
    if (lane == 0) { g_as[gw] = s; g_ad[gw] = d; }
}

// ---------------- scatter into CSR + per-edge exp ----------------------------
__global__ void scatter_kernel(const void* __restrict__ idx) {
    int e = blockIdx.x * blockDim.x + threadIdx.x;
    if (e >= EE) return;
    int s, d;
    if (g_is64) {
        const long long* q = (const long long*)idx;
        s = (int)q[e]; d = (int)q[EE + e];
    } else {
        const int* q = (const int*)idx;
        s = q[e]; d = q[EE + e];
    }
    float v = g_as[s] + g_ad[d];
    v = (v > 0.f) ? v : 0.2f * v;
    float ex = expf(v);
    int p = atomicAdd(&g_pos[d], 1);
    g_srcs[p] = s;
    g_exs[p] = ex;
}

// ---------------- CSR aggregation: warp per destination node -----------------
__global__ void agg_kernel() {
    int node = (int)((blockIdx.x * (size_t)blockDim.x + threadIdx.x) >> 5);
    int lane = threadIdx.x & 31;
    if (node >= NN) return;
    int beg = g_off[node];
    int cnt = g_cnt[node];
    // self loop term
    float v = g_as[node] + g_ad[node];
    v = (v > 0.f) ? v : 0.2f * v;
    float ex_self = expf(v);
    // denominator
    float dsum = 0.f;
    for (int i = lane; i < cnt; i += 32) dsum += g_exs[beg + i];
#pragma unroll
    for (int o = 16; o; o >>= 1) dsum += __shfl_xor_sync(0xffffffffu, dsum, o);
    float invd = 1.f / (dsum + ex_self + 1e-16f);
    // accumulate 64 features (2 per lane)
    float2 acc;
    {
        float2 hv = *(const float2*)(g_h + (size_t)node * 64 + lane * 2);
        float c = ex_self * invd;
        acc.x = c * hv.x; acc.y = c * hv.y;
    }
#pragma unroll 4
    for (int e = 0; e < cnt; e++) {
        int s = g_srcs[beg + e];
        float c = g_exs[beg + e] * invd;
        float2 hv = *(const float2*)(g_h + (size_t)s * 64 + lane * 2);
        acc.x += c * hv.x; acc.y += c * hv.y;
    }
    *(float2*)(g_x3 + (size_t)node * 64 + lane * 2) = acc;
}

// ---------------- fp32 GEMM: BM=128, BK=16, 8x8 microtile ---------------------
// BN=128 -> 256 threads; BN=64 -> 128 threads.
template<int BN, int NTHR>
__global__ void __launch_bounds__(NTHR)
gemm_kernel(const float* __restrict__ A, int lda, int acol,
            const float* __restrict__ W, int ldw, int wrow0,
            const float* __restrict__ bias,
            float* __restrict__ C, int ldc,
            int n, int K, int do_relu,
            const float* __restrict__ xr,
            const float* __restrict__ u1,
            const float* __restrict__ u2,
            const float* __restrict__ cc) {
    constexpr int BM = 128, BK = 16;
    __shared__ float As[BK][BM + 4];   // +4 keeps 16B alignment for float4 reads
    __shared__ float Ws[BK][BN];
    const int tid = threadIdx.x;
    const int tx = tid % (BN / 8);
    const int ty = tid / (BN / 8);
    const int row0 = blockIdx.x * BM;
    const int col0 = blockIdx.y * BN;
    float acc[8][8] = {};

    for (int kk = 0; kk < K; kk += BK) {
        // A tile: scalar loads (coalesced along k), transposed store
#pragma unroll
        for (int l = 0; l < (BM * BK) / NTHR; l++) {
            int i = tid + l * NTHR;
            int c = i & (BK - 1), r = i >> 4;
            int gr = row0 + r;
            As[c][r] = (gr < n) ? A[(size_t)gr * lda + acol + kk + c] : 0.f;
        }
        // W tile: float4 loads
#pragma unroll
        for (int l = 0; l < (BK * BN / 4) / NTHR; l++) {
            int i = tid + l * NTHR;
            int r = i / (BN / 4), c4 = i % (BN / 4);
            *(float4*)&Ws[r][c4 * 4] =
                *(const float4*)&W[(size_t)(wrow0 + kk + r) * ldw + col0 + c4 * 4];
        }
        __syncthreads();
#pragma unroll
        for (int k = 0; k < BK; k++) {
            float a[8], b[8];
            *(float4*)&a[0] = *(const float4*)&As[k][ty * 8];
            *(float4*)&a[4] = *(const float4*)&As[k][ty * 8 + 4];
            *(float4*)&b[0] = *(const float4*)&Ws[k][tx * 8];
            *(float4*)&b[4] = *(const float4*)&Ws[k][tx * 8 + 4];
#pragma unroll
            for (int i = 0; i < 8; i++)
#pragma unroll
                for (int j = 0; j < 8; j++)
                    acc[i][j] += a[i] * b[j];
        }
        __syncthreads();
    }

    // per-thread column constants
    float bj[8], u1j[8], u2j[8], ccj[8];
#pragma unroll
    for (int j = 0; j < 8; j++) {
        int c = col0 + tx * 8 + j;
        bj[j]  = bias ? bias[c] : 0.f;
        u1j[j] = xr ? u1[c] : 0.f;
        u2j[j] = xr ? u2[c] : 0.f;
        ccj[j] = xr ? cc[c] : 0.f;
    }
#pragma unroll
    for (int i = 0; i < 8; i++) {
        int r = row0 + ty * 8 + i;
        if (r >= n) continue;
        float xa = 0.f, xb = 0.f;
        if (xr) { xa = xr[(size_t)r * 130]; xb = xr[(size_t)r * 130 + 1]; }
        float v[8];
#pragma unroll
        for (int j = 0; j < 8; j++) {
            float t = acc[i][j] + bj[j];
            if (xr) t += xa * u1j[j] + xb * u2j[j] + ccj[j];
            if (do_relu) t = fmaxf(t, 0.f);
            v[j] = t;
        }
        float* cp = &C[(size_t)r * ldc + col0 + tx * 8];
        *(float4*)cp       = make_float4(v[0], v[1], v[2], v[3]);
        *(float4*)(cp + 4) = make_float4(v[4], v[5], v[6], v[7]);
    }
}

// -----------------------------------------------------------------------------
extern "C" void kernel_launch(void* const* d_in, const int* in_sizes, int n_in,
                              void* d_out, int out_size) {
    const float* x    = (const float*)d_in[0];
    const void*  ei   = d_in[1];
    const float* w1   = (const float*)d_in[2];
    const float* b1   = (const float*)d_in[3];
    const float* w2   = (const float*)d_in[4];
    const float* b2   = (const float*)d_in[5];
    const float* gatw = (const float*)d_in[6];
    const float* asrc = (const float*)d_in[7];
    const float* adst = (const float*)d_in[8];
    const float* gatb = (const float*)d_in[9];
    const float* fc1w = (const float*)d_in[10];
    const float* fc1b = (const float*)d_in[11];
    const float* fc2w = (const float*)d_in[12];
    const float* fc2b = (const float*)d_in[13];
    const float* fc3w = (const float*)d_in[14];
    const float* fc3b = (const float*)d_in[15];
    float* out = (float*)d_out;

    void *ph, *px3, *ph1, *ph2, *pu1, *pu2, *pcc;
    cudaGetSymbolAddress(&ph,  g_h);
    cudaGetSymbolAddress(&px3, g_x3);
    cudaGetSymbolAddress(&ph1, g_h1);
    cudaGetSymbolAddress(&ph2, g_h2);
    cudaGetSymbolAddress(&pu1, g_u1);
    cudaGetSymbolAddress(&pu2, g_u2);
    cudaGetSymbolAddress(&pcc, g_cc);

    const int GX = (NN + 127) / 128;   // 782

    detect_kernel<<<1, 256>>>((const unsigned*)ei);
    prep_kernel<<<1, 384>>>(w1, b1, w2, b2, gatb, fc1w, fc1b);
    zero_cnt_kernel<<<(NN + 255) / 256, 256>>>();

    // CSR build (needs only edge_index)
    hist_kernel<<<(EE + 255) / 256, 256>>>(ei);
    scan1_kernel<<<NSB, 256>>>();
    scan2_kernel<<<1, 256>>>();
    scan3_kernel<<<NSB, 512>>>();

    // h = x[:,2:130] @ gat_w        (K=128, 64 cols)
    gemm_kernel<64, 128><<<dim3(GX, 1), 128>>>(x, 130, 2, gatw, 64, 0, nullptr,
                                               (float*)ph, 64, NN, 128, 0,
                                               nullptr, nullptr, nullptr, nullptr);
    // per-node attention logits
    alpha_kernel<<<(NN * 32 + 255) / 256, 256>>>(asrc, adst);
    // scatter edges into CSR with per-edge exp
    scatter_kernel<<<(EE + 255) / 256, 256>>>(ei);
    // softmax-normalized aggregation (no atomics)
    agg_kernel<<<(NN * 32 + 255) / 256, 256>>>();

    // fc1: relu( x3 @ fc1_w[128:192,:] + x0*u1 + x1*u2 + cc )   (K=64, 384 cols)
    gemm_kernel<128, 256><<<dim3(GX, 3), 256>>>((const float*)px3, 64, 0, fc1w, 384, 128, nullptr,
                                                (float*)ph1, 384, NN, 64, 1,
                                                x, (const float*)pu1, (const float*)pu2, (const float*)pcc);
    // fc2: relu( h1 @ fc2_w + fc2_b )                            (K=384, 128 cols)
    gemm_kernel<128, 256><<<dim3(GX, 1), 256>>>((const float*)ph1, 384, 0, fc2w, 128, 0, fc2b,
                                                (float*)ph2, 128, NN, 384, 1,
                                                nullptr, nullptr, nullptr, nullptr);
    // fc3: h2 @ fc3_w + fc3_b                                    (K=128, 64 cols)
    gemm_kernel<64, 128><<<dim3(GX, 1), 128>>>((const float*)ph2, 128, 0, fc3w, 64, 0, fc3b,
                                               out, 64, NN, 128, 0,
                                               nullptr, nullptr, nullptr, nullptr);
}

// round 3
// speedup vs baseline: 1.2478x; 1.0401x over previous
#include <cuda_runtime.h>
#include <math.h>

#define NN 100000
#define EE 1600000
#define NSB ((NN + 511) / 512)   // 196 scan blocks

// ---------------- scratch (device globals; no allocation allowed) ------------
__device__ float g_h  [(size_t)NN * 64];    // GAT h = x[:,2:] @ gat_w
__device__ float g_x3 [(size_t)NN * 64];    // aggregated GAT output (pre-bias)
__device__ float g_h1 [(size_t)NN * 384];   // fc1 activation
__device__ float g_h2 [(size_t)NN * 128];   // fc2 activation
__device__ float g_as [NN];
__device__ float g_ad [NN];
__device__ int   g_cnt[NN];                 // in-degree
__device__ int   g_off[NN];                 // CSR row offsets (exclusive scan)
__device__ int   g_pos[NN];                 // scatter cursors
__device__ int   g_srcs[EE];                // CSR src indices
__device__ float g_exs [EE];                // per-edge exp(leakyrelu(...))
__device__ int   g_bsum[NSB], g_boff[NSB];
__device__ float g_u1[384], g_u2[384], g_cc[384];
__device__ int   g_is64;

// ---------------- int32/int64 edge-index detection ---------------------------
__global__ void detect_kernel(const unsigned* __restrict__ p) {
    __shared__ unsigned sh[256];
    sh[threadIdx.x] = p[2 * threadIdx.x + 1];
    __syncthreads();
    if (threadIdx.x == 0) {
        unsigned o = 0;
        for (int i = 0; i < 256; i++) o |= sh[i];
        g_is64 = (o == 0) ? 1 : 0;
    }
}

// ---------------- precompute rank-2 epilogue vectors for fc1 -----------------
__global__ void prep_kernel(const float* __restrict__ w1, const float* __restrict__ b1,
                            const float* __restrict__ w2, const float* __restrict__ b2,
                            const float* __restrict__ gatb,
                            const float* __restrict__ fc1w, const float* __restrict__ fc1b) {
    int k = threadIdx.x;  // 384 threads
    float s1 = 0.f, s2 = 0.f, c = fc1b[k];
    for (int j = 0; j < 64; j++) {
        float wa = fc1w[(size_t)j * 384 + k];
        float wb = fc1w[(size_t)(64 + j) * 384 + k];
        float wc = fc1w[(size_t)(128 + j) * 384 + k];
        s1 += w1[j] * wa;
        s2 += w2[j] * wb;
        c  += b1[j] * wa + b2[j] * wb + gatb[j] * wc;
    }
    g_u1[k] = s1; g_u2[k] = s2; g_cc[k] = c;
}

__global__ void zero_cnt_kernel() {
    int i = blockIdx.x * blockDim.x + threadIdx.x;
    if (i < NN) g_cnt[i] = 0;
}

// ---------------- degree histogram -------------------------------------------
__global__ void hist_kernel(const void* __restrict__ idx) {
    int e = blockIdx.x * blockDim.x + threadIdx.x;
    if (e >= EE) return;
    int d = g_is64 ? (int)((const long long*)idx)[EE + e]
                   : ((const int*)idx)[EE + e];
    atomicAdd(&g_cnt[d], 1);
}

// ---------------- 3-kernel exclusive scan over g_cnt -------------------------
__global__ void scan1_kernel() {               // grid NSB, 256 thr
    __shared__ int sh[256];
    int b = blockIdx.x, t = threadIdx.x;
    int i0 = b * 512 + t;
    int v = 0;
    if (i0 < NN) v += g_cnt[i0];
    if (i0 + 256 < NN) v += g_cnt[i0 + 256];
    sh[t] = v; __syncthreads();
    for (int o = 128; o; o >>= 1) { if (t < o) sh[t] += sh[t + o]; __syncthreads(); }
    if (t == 0) g_bsum[b] = sh[0];
}

__global__ void scan2_kernel() {               // 1 block, 256 thr (NSB <= 256)
    __shared__ int sh[256];
    int t = threadIdx.x;
    int v = (t < NSB) ? g_bsum[t] : 0;
    sh[t] = v;
    for (int o = 1; o < 256; o <<= 1) {
        __syncthreads();
        int u = (t >= o) ? sh[t - o] : 0;
        __syncthreads();
        sh[t] += u;
    }
    __syncthreads();
    if (t < NSB) g_boff[t] = sh[t] - v;        // exclusive
}

__global__ void scan3_kernel() {               // grid NSB, 512 thr
    __shared__ int sh[512];
    int b = blockIdx.x, t = threadIdx.x;
    int i = b * 512 + t;
    int c = (i < NN) ? g_cnt[i] : 0;
    sh[t] = c;
    for (int o = 1; o < 512; o <<= 1) {
        __syncthreads();
        int u = (t >= o) ? sh[t - o] : 0;
        __syncthreads();
        sh[t] += u;
    }
    __syncthreads();
    if (i < NN) {
        int excl = sh[t] - c + g_boff[b];
        g_off[i] = excl;
        g_pos[i] = excl;
    }
}

// ---------------- alpha_src / alpha_dst per node (warp per node) -------------
__global__ void alpha_kernel(const float* __restrict__ asrc, const float* __restrict__ adst) {
    int gw = (int)((blockIdx.x * blockDim.x + threadIdx.x) >> 5);
    int lane = threadIdx.x & 31;
    if (gw >= NN) return;
    float h0 = g_h[(size_t)gw * 64 + lane];
    float h1 = g_h[(size_t)gw * 64 + 32 + lane];
    float s = h0 * asrc[lane] + h1 * asrc[32 + lane];
    float d = h0 * adst[lane] + h1 * adst[32 + lane];
#pragma unroll
    for (int o = 16; o; o >>= 1) {
        s += __shfl_xor_sync(0xffffffffu, s, o);
        d += __shfl_xor_sync(0xffffffffu, d, o);
    }
    if (lane == 0) { g_as[gw] = s; g_ad[gw] = d; }
}

// ---------------- scatter into CSR + per-edge exp ----------------------------
__global__ void scatter_kernel(const void* __restrict__ idx) {
    int e = blockIdx.x * blockDim.x + threadIdx.x;
    if (e >= EE) return;
    int s, d;
    if (g_is64) {
        const long long* q = (const long long*)idx;
        s = (int)q[e]; d = (int)q[EE + e];
    } else {
        const int* q = (const int*)idx;
        s = q[e]; d = q[EE + e];
    }
    float v = g_as[s] + g_ad[d];
    v = (v > 0.f) ? v : 0.2f * v;
    float ex = expf(v);
    int p = atomicAdd(&g_pos[d], 1);
    g_srcs[p] = s;
    g_exs[p] = ex;
}

// ---------------- CSR aggregation: warp per destination node -----------------
__global__ void agg_kernel() {
    int node = (int)((blockIdx.x * (size_t)blockDim.x + threadIdx.x) >> 5);
    int lane = threadIdx.x & 31;
    if (node >= NN) return;
    int beg = g_off[node];
    int cnt = g_cnt[node];
    // self loop term
    float v = g_as[node] + g_ad[node];
    v = (v > 0.f) ? v : 0.2f * v;
    float ex_self = expf(v);
    // denominator
    float dsum = 0.f;
    for (int i = lane; i < cnt; i += 32) dsum += g_exs[beg + i];
#pragma unroll
    for (int o = 16; o; o >>= 1) dsum += __shfl_xor_sync(0xffffffffu, dsum, o);
    float invd = 1.f / (dsum + ex_self + 1e-16f);
    // accumulate 64 features (2 per lane)
    float2 acc;
    {
        float2 hv = *(const float2*)(g_h + (size_t)node * 64 + lane * 2);
        float c = ex_self * invd;
        acc.x = c * hv.x; acc.y = c * hv.y;
    }
#pragma unroll 4
    for (int e = 0; e < cnt; e++) {
        int s = g_srcs[beg + e];
        float c = g_exs[beg + e] * invd;
        float2 hv = *(const float2*)(g_h + (size_t)s * 64 + lane * 2);
        acc.x += c * hv.x; acc.y += c * hv.y;
    }
    *(float2*)(g_x3 + (size_t)node * 64 + lane * 2) = acc;
}

// ---------------- fp32 GEMM: BM=128, BK=16, 8x8 microtile ---------------------
// BN=128 -> 256 threads; BN=64 -> 128 threads.
template<int BN, int NTHR>
__global__ void __launch_bounds__(NTHR)
gemm_kernel(const float* __restrict__ A, int lda, int acol,
            const float* __restrict__ W, int ldw, int wrow0,
            const float* __restrict__ bias,
            float* __restrict__ C, int ldc,
            int n, int K, int do_relu,
            const float* __restrict__ xr,
            const float* __restrict__ u1,
            const float* __restrict__ u2,
            const float* __restrict__ cc) {
    constexpr int BM = 128, BK = 16;
    __shared__ float As[BK][BM + 4];   // +4 keeps 16B alignment for float4 reads
    __shared__ float Ws[BK][BN];
    const int tid = threadIdx.x;
    const int tx = tid % (BN / 8);
    const int ty = tid / (BN / 8);
    const int row0 = blockIdx.x * BM;
    const int col0 = blockIdx.y * BN;
    float acc[8][8] = {};

    for (int kk = 0; kk < K; kk += BK) {
        // A tile: scalar loads (coalesced along k), transposed store
#pragma unroll
        for (int l = 0; l < (BM * BK) / NTHR; l++) {
            int i = tid + l * NTHR;
            int c = i & (BK - 1), r = i >> 4;
            int gr = row0 + r;
            As[c][r] = (gr < n) ? A[(size_t)gr * lda + acol + kk + c] : 0.f;
        }
        // W tile: float4 loads
#pragma unroll
        for (int l = 0; l < (BK * BN / 4) / NTHR; l++) {
            int i = tid + l * NTHR;
            int r = i / (BN / 4), c4 = i % (BN / 4);
            *(float4*)&Ws[r][c4 * 4] =
                *(const float4*)&W[(size_t)(wrow0 + kk + r) * ldw + col0 + c4 * 4];
        }
        __syncthreads();
#pragma unroll
        for (int k = 0; k < BK; k++) {
            float a[8], b[8];
            *(float4*)&a[0] = *(const float4*)&As[k][ty * 8];
            *(float4*)&a[4] = *(const float4*)&As[k][ty * 8 + 4];
            *(float4*)&b[0] = *(const float4*)&Ws[k][tx * 8];
            *(float4*)&b[4] = *(const float4*)&Ws[k][tx * 8 + 4];
#pragma unroll
            for (int i = 0; i < 8; i++)
#pragma unroll
                for (int j = 0; j < 8; j++)
                    acc[i][j] += a[i] * b[j];
        }
        __syncthreads();
    }

    // per-thread column constants
    float bj[8], u1j[8], u2j[8], ccj[8];
#pragma unroll
    for (int j = 0; j < 8; j++) {
        int c = col0 + tx * 8 + j;
        bj[j]  = bias ? bias[c] : 0.f;
        u1j[j] = xr ? u1[c] : 0.f;
        u2j[j] = xr ? u2[c] : 0.f;
        ccj[j] = xr ? cc[c] : 0.f;
    }
#pragma unroll
    for (int i = 0; i < 8; i++) {
        int r = row0 + ty * 8 + i;
        if (r >= n) continue;
        float xa = 0.f, xb = 0.f;
        if (xr) { xa = xr[(size_t)r * 130]; xb = xr[(size_t)r * 130 + 1]; }
        float v[8];
#pragma unroll
        for (int j = 0; j < 8; j++) {
            float t = acc[i][j] + bj[j];
            if (xr) t += xa * u1j[j] + xb * u2j[j] + ccj[j];
            if (do_relu) t = fmaxf(t, 0.f);
            v[j] = t;
        }
        float* cp = &C[(size_t)r * ldc + col0 + tx * 8];
        *(float4*)cp       = make_float4(v[0], v[1], v[2], v[3]);
        *(float4*)(cp + 4) = make_float4(v[4], v[5], v[6], v[7]);
    }
}

// -----------------------------------------------------------------------------
extern "C" void kernel_launch(void* const* d_in, const int* in_sizes, int n_in,
                              void* d_out, int out_size) {
    const float* x    = (const float*)d_in[0];
    const void*  ei   = d_in[1];
    const float* w1   = (const float*)d_in[2];
    const float* b1   = (const float*)d_in[3];
    const float* w2   = (const float*)d_in[4];
    const float* b2   = (const float*)d_in[5];
    const float* gatw = (const float*)d_in[6];
    const float* asrc = (const float*)d_in[7];
    const float* adst = (const float*)d_in[8];
    const float* gatb = (const float*)d_in[9];
    const float* fc1w = (const float*)d_in[10];
    const float* fc1b = (const float*)d_in[11];
    const float* fc2w = (const float*)d_in[12];
    const float* fc2b = (const float*)d_in[13];
    const float* fc3w = (const float*)d_in[14];
    const float* fc3b = (const float*)d_in[15];
    float* out = (float*)d_out;

    void *ph, *px3, *ph1, *ph2, *pu1, *pu2, *pcc;
    cudaGetSymbolAddress(&ph,  g_h);
    cudaGetSymbolAddress(&px3, g_x3);
    cudaGetSymbolAddress(&ph1, g_h1);
    cudaGetSymbolAddress(&ph2, g_h2);
    cudaGetSymbolAddress(&pu1, g_u1);
    cudaGetSymbolAddress(&pu2, g_u2);
    cudaGetSymbolAddress(&pcc, g_cc);

    const int GX = (NN + 127) / 128;   // 782

    detect_kernel<<<1, 256>>>((const unsigned*)ei);
    prep_kernel<<<1, 384>>>(w1, b1, w2, b2, gatb, fc1w, fc1b);
    zero_cnt_kernel<<<(NN + 255) / 256, 256>>>();

    // CSR build (needs only edge_index)
    hist_kernel<<<(EE + 255) / 256, 256>>>(ei);
    scan1_kernel<<<NSB, 256>>>();
    scan2_kernel<<<1, 256>>>();
    scan3_kernel<<<NSB, 512>>>();

    // h = x[:,2:130] @ gat_w        (K=128, 64 cols)
    gemm_kernel<64, 128><<<dim3(GX, 1), 128>>>(x, 130, 2, gatw, 64, 0, nullptr,
                                               (float*)ph, 64, NN, 128, 0,
                                               nullptr, nullptr, nullptr, nullptr);
    // per-node attention logits
    alpha_kernel<<<(NN * 32 + 255) / 256, 256>>>(asrc, adst);
    // scatter edges into CSR with per-edge exp
    scatter_kernel<<<(EE + 255) / 256, 256>>>(ei);
    // softmax-normalized aggregation (no atomics)
    agg_kernel<<<(NN * 32 + 255) / 256, 256>>>();

    // fc1: relu( x3 @ fc1_w[128:192,:] + x0*u1 + x1*u2 + cc )   (K=64, 384 cols)
    gemm_kernel<128, 256><<<dim3(GX, 3), 256>>>((const float*)px3, 64, 0, fc1w, 384, 128, nullptr,
                                                (float*)ph1, 384, NN, 64, 1,
                                                x, (const float*)pu1, (const float*)pu2, (const float*)pcc);
    // fc2: relu( h1 @ fc2_w + fc2_b )                            (K=384, 128 cols)
    gemm_kernel<128, 256><<<dim3(GX, 1), 256>>>((const float*)ph1, 384, 0, fc2w, 128, 0, fc2b,
                                                (float*)ph2, 128, NN, 384, 1,
                                                nullptr, nullptr, nullptr, nullptr);
    // fc3: h2 @ fc3_w + fc3_b                                    (K=128, 64 cols)
    gemm_kernel<64, 128><<<dim3(GX, 1), 128>>>((const float*)ph2, 128, 0, fc3w, 64, 0, fc3b,
                                               out, 64, NN, 128, 0,
                                               nullptr, nullptr, nullptr, nullptr);
}

// round 4
// speedup vs baseline: 1.2486x; 1.0006x over previous
#include <cuda_runtime.h>
#include <math.h>

#define NN 100000
#define EE 1600000
#define NSB ((NN + 511) / 512)   // 196 scan blocks

// ---------------- scratch (device globals; no allocation allowed) ------------
__device__ float g_h  [(size_t)NN * 64];    // GAT h = x[:,2:] @ gat_w
__device__ float g_x3 [(size_t)NN * 64];    // aggregated GAT output (pre-bias)
__device__ float g_h1 [(size_t)NN * 384];   // fc1 activation
__device__ float g_h2 [(size_t)NN * 128];   // fc2 activation
__device__ float g_as [NN];
__device__ float g_ad [NN];
__device__ int   g_cnt[NN];                 // in-degree
__device__ int   g_off[NN];                 // CSR row offsets (exclusive scan)
__device__ int   g_pos[NN];                 // scatter cursors
__device__ int   g_srcs[EE];                // CSR src indices
__device__ float g_exs [EE];                // per-edge exp(leakyrelu(...))
__device__ int   g_bsum[NSB], g_boff[NSB];
__device__ float g_u1[384], g_u2[384], g_cc[384];
__device__ int   g_is64;

// ---------------- int32/int64 edge-index detection ---------------------------
__global__ void detect_kernel(const unsigned* __restrict__ p) {
    __shared__ unsigned sh[256];
    sh[threadIdx.x] = p[2 * threadIdx.x + 1];
    __syncthreads();
    if (threadIdx.x == 0) {
        unsigned o = 0;
        for (int i = 0; i < 256; i++) o |= sh[i];
        g_is64 = (o == 0) ? 1 : 0;
    }
}

// ---------------- precompute rank-2 epilogue vectors for fc1 -----------------
__global__ void prep_kernel(const float* __restrict__ w1, const float* __restrict__ b1,
                            const float* __restrict__ w2, const float* __restrict__ b2,
                            const float* __restrict__ gatb,
                            const float* __restrict__ fc1w, const float* __restrict__ fc1b) {
    int k = threadIdx.x;  // 384 threads
    float s1 = 0.f, s2 = 0.f, c = fc1b[k];
    for (int j = 0; j < 64; j++) {
        float wa = fc1w[(size_t)j * 384 + k];
        float wb = fc1w[(size_t)(64 + j) * 384 + k];
        float wc = fc1w[(size_t)(128 + j) * 384 + k];
        s1 += w1[j] * wa;
        s2 += w2[j] * wb;
        c  += b1[j] * wa + b2[j] * wb + gatb[j] * wc;
    }
    g_u1[k] = s1; g_u2[k] = s2; g_cc[k] = c;
}

__global__ void zero_cnt_kernel() {
    int i = blockIdx.x * blockDim.x + threadIdx.x;
    if (i < NN) g_cnt[i] = 0;
}

// ---------------- degree histogram -------------------------------------------
__global__ void hist_kernel(const void* __restrict__ idx) {
    int e = blockIdx.x * blockDim.x + threadIdx.x;
    if (e >= EE) return;
    int d = g_is64 ? (int)((const long long*)idx)[EE + e]
                   : ((const int*)idx)[EE + e];
    atomicAdd(&g_cnt[d], 1);
}

// ---------------- 3-kernel exclusive scan over g_cnt -------------------------
__global__ void scan1_kernel() {               // grid NSB, 256 thr
    __shared__ int sh[256];
    int b = blockIdx.x, t = threadIdx.x;
    int i0 = b * 512 + t;
    int v = 0;
    if (i0 < NN) v += g_cnt[i0];
    if (i0 + 256 < NN) v += g_cnt[i0 + 256];
    sh[t] = v; __syncthreads();
    for (int o = 128; o; o >>= 1) { if (t < o) sh[t] += sh[t + o]; __syncthreads(); }
    if (t == 0) g_bsum[b] = sh[0];
}

__global__ void scan2_kernel() {               // 1 block, 256 thr (NSB <= 256)
    __shared__ int sh[256];
    int t = threadIdx.x;
    int v = (t < NSB) ? g_bsum[t] : 0;
    sh[t] = v;
    for (int o = 1; o < 256; o <<= 1) {
        __syncthreads();
        int u = (t >= o) ? sh[t - o] : 0;
        __syncthreads();
        sh[t] += u;
    }
    __syncthreads();
    if (t < NSB) g_boff[t] = sh[t] - v;        // exclusive
}

__global__ void scan3_kernel() {               // grid NSB, 512 thr
    __shared__ int sh[512];
    int b = blockIdx.x, t = threadIdx.x;
    int i = b * 512 + t;
    int c = (i < NN) ? g_cnt[i] : 0;
    sh[t] = c;
    for (int o = 1; o < 512; o <<= 1) {
        __syncthreads();
        int u = (t >= o) ? sh[t - o] : 0;
        __syncthreads();
        sh[t] += u;
    }
    __syncthreads();
    if (i < NN) {
        int excl = sh[t] - c + g_boff[b];
        g_off[i] = excl;
        g_pos[i] = excl;
    }
}

// ---------------- alpha_src / alpha_dst per node (warp per node) -------------
__global__ void alpha_kernel(const float* __restrict__ asrc, const float* __restrict__ adst) {
    int gw = (int)((blockIdx.x * blockDim.x + threadIdx.x) >> 5);
    int lane = threadIdx.x & 31;
    if (gw >= NN) return;
    float h0 = g_h[(size_t)gw * 64 + lane];
    float h1 = g_h[(size_t)gw * 64 + 32 + lane];
    float s = h0 * asrc[lane] + h1 * asrc[32 + lane];
    float d = h0 * adst[lane] + h1 * adst[32 + lane];
#pragma unroll
    for (int o = 16; o; o >>= 1) {
        s += __shfl_xor_sync(0xffffffffu, s, o);
        d += __shfl_xor_sync(0xffffffffu, d, o);
    }
    if (lane == 0) { g_as[gw] = s; g_ad[gw] = d; }
}

// ---------------- scatter into CSR + per-edge exp ----------------------------
__global__ void scatter_kernel(const void* __restrict__ idx) {
    int e = blockIdx.x * blockDim.x + threadIdx.x;
    if (e >= EE) return;
    int s, d;
    if (g_is64) {
        const long long* q = (const long long*)idx;
        s = (int)q[e]; d = (int)q[EE + e];
    } else {
        const int* q = (const int*)idx;
        s = q[e]; d = q[EE + e];
    }
    float v = g_as[s] + g_ad[d];
    v = (v > 0.f) ? v : 0.2f * v;
    float ex = expf(v);
    int p = atomicAdd(&g_pos[d], 1);
    g_srcs[p] = s;
    g_exs[p] = ex;
}

// ---------------- CSR aggregation: warp per destination node -----------------
__global__ void agg_kernel() {
    int node = (int)((blockIdx.x * (size_t)blockDim.x + threadIdx.x) >> 5);
    int lane = threadIdx.x & 31;
    if (node >= NN) return;
    int beg = g_off[node];
    int cnt = g_cnt[node];
    // self loop term
    float v = g_as[node] + g_ad[node];
    v = (v > 0.f) ? v : 0.2f * v;
    float ex_self = expf(v);
    // denominator
    float dsum = 0.f;
    for (int i = lane; i < cnt; i += 32) dsum += g_exs[beg + i];
#pragma unroll
    for (int o = 16; o; o >>= 1) dsum += __shfl_xor_sync(0xffffffffu, dsum, o);
    float invd = 1.f / (dsum + ex_self + 1e-16f);
    // accumulate 64 features (2 per lane)
    float2 acc;
    {
        float2 hv = *(const float2*)(g_h + (size_t)node * 64 + lane * 2);
        float c = ex_self * invd;
        acc.x = c * hv.x; acc.y = c * hv.y;
    }
#pragma unroll 4
    for (int e = 0; e < cnt; e++) {
        int s = g_srcs[beg + e];
        float c = g_exs[beg + e] * invd;
        float2 hv = *(const float2*)(g_h + (size_t)s * 64 + lane * 2);
        acc.x += c * hv.x; acc.y += c * hv.y;
    }
    *(float2*)(g_x3 + (size_t)node * 64 + lane * 2) = acc;
}

// ---------------- fp32 GEMM: BM=128, BK=16, 8x8 microtile ---------------------
// BN=128 -> 256 threads; BN=64 -> 128 threads.
template<int BN, int NTHR>
__global__ void __launch_bounds__(NTHR)
gemm_kernel(const float* __restrict__ A, int lda, int acol,
            const float* __restrict__ W, int ldw, int wrow0,
            const float* __restrict__ bias,
            float* __restrict__ C, int ldc,
            int n, int K, int do_relu,
            const float* __restrict__ xr,
            const float* __restrict__ u1,
            const float* __restrict__ u2,
            const float* __restrict__ cc) {
    constexpr int BM = 128, BK = 16;
    __shared__ float As[BK][BM + 4];   // +4 keeps 16B alignment for float4 reads
    __shared__ float Ws[BK][BN];
    const int tid = threadIdx.x;
    const int tx = tid % (BN / 8);
    const int ty = tid / (BN / 8);
    const int row0 = blockIdx.x * BM;
    const int col0 = blockIdx.y * BN;
    float acc[8][8] = {};

    for (int kk = 0; kk < K; kk += BK) {
        // A tile: scalar loads (coalesced along k), transposed store
#pragma unroll
        for (int l = 0; l < (BM * BK) / NTHR; l++) {
            int i = tid + l * NTHR;
            int c = i & (BK - 1), r = i >> 4;
            int gr = row0 + r;
            As[c][r] = (gr < n) ? A[(size_t)gr * lda + acol + kk + c] : 0.f;
        }
        // W tile: float4 loads
#pragma unroll
        for (int l = 0; l < (BK * BN / 4) / NTHR; l++) {
            int i = tid + l * NTHR;
            int r = i / (BN / 4), c4 = i % (BN / 4);
            *(float4*)&Ws[r][c4 * 4] =
                *(const float4*)&W[(size_t)(wrow0 + kk + r) * ldw + col0 + c4 * 4];
        }
        __syncthreads();
#pragma unroll
        for (int k = 0; k < BK; k++) {
            float a[8], b[8];
            *(float4*)&a[0] = *(const float4*)&As[k][ty * 8];
            *(float4*)&a[4] = *(const float4*)&As[k][ty * 8 + 4];
            *(float4*)&b[0] = *(const float4*)&Ws[k][tx * 8];
            *(float4*)&b[4] = *(const float4*)&Ws[k][tx * 8 + 4];
#pragma unroll
            for (int i = 0; i < 8; i++)
#pragma unroll
                for (int j = 0; j < 8; j++)
                    acc[i][j] += a[i] * b[j];
        }
        __syncthreads();
    }

    // per-thread column constants
    float bj[8], u1j[8], u2j[8], ccj[8];
#pragma unroll
    for (int j = 0; j < 8; j++) {
        int c = col0 + tx * 8 + j;
        bj[j]  = bias ? bias[c] : 0.f;
        u1j[j] = xr ? u1[c] : 0.f;
        u2j[j] = xr ? u2[c] : 0.f;
        ccj[j] = xr ? cc[c] : 0.f;
    }
#pragma unroll
    for (int i = 0; i < 8; i++) {
        int r = row0 + ty * 8 + i;
        if (r >= n) continue;
        float xa = 0.f, xb = 0.f;
        if (xr) { xa = xr[(size_t)r * 130]; xb = xr[(size_t)r * 130 + 1]; }
        float v[8];
#pragma unroll
        for (int j = 0; j < 8; j++) {
            float t = acc[i][j] + bj[j];
            if (xr) t += xa * u1j[j] + xb * u2j[j] + ccj[j];
            if (do_relu) t = fmaxf(t, 0.f);
            v[j] = t;
        }
        float* cp = &C[(size_t)r * ldc + col0 + tx * 8];
        *(float4*)cp       = make_float4(v[0], v[1], v[2], v[3]);
        *(float4*)(cp + 4) = make_float4(v[4], v[5], v[6], v[7]);
    }
}

// -----------------------------------------------------------------------------
extern "C" void kernel_launch(void* const* d_in, const int* in_sizes, int n_in,
                              void* d_out, int out_size) {
    const float* x    = (const float*)d_in[0];
    const void*  ei   = d_in[1];
    const float* w1   = (const float*)d_in[2];
    const float* b1   = (const float*)d_in[3];
    const float* w2   = (const float*)d_in[4];
    const float* b2   = (const float*)d_in[5];
    const float* gatw = (const float*)d_in[6];
    const float* asrc = (const float*)d_in[7];
    const float* adst = (const float*)d_in[8];
    const float* gatb = (const float*)d_in[9];
    const float* fc1w = (const float*)d_in[10];
    const float* fc1b = (const float*)d_in[11];
    const float* fc2w = (const float*)d_in[12];
    const float* fc2b = (const float*)d_in[13];
    const float* fc3w = (const float*)d_in[14];
    const float* fc3b = (const float*)d_in[15];
    float* out = (float*)d_out;

    void *ph, *px3, *ph1, *ph2, *pu1, *pu2, *pcc;
    cudaGetSymbolAddress(&ph,  g_h);
    cudaGetSymbolAddress(&px3, g_x3);
    cudaGetSymbolAddress(&ph1, g_h1);
    cudaGetSymbolAddress(&ph2, g_h2);
    cudaGetSymbolAddress(&pu1, g_u1);
    cudaGetSymbolAddress(&pu2, g_u2);
    cudaGetSymbolAddress(&pcc, g_cc);

    const int GX = (NN + 127) / 128;   // 782

    detect_kernel<<<1, 256>>>((const unsigned*)ei);
    prep_kernel<<<1, 384>>>(w1, b1, w2, b2, gatb, fc1w, fc1b);
    zero_cnt_kernel<<<(NN + 255) / 256, 256>>>();

    // CSR build (needs only edge_index)
    hist_kernel<<<(EE + 255) / 256, 256>>>(ei);
    scan1_kernel<<<NSB, 256>>>();
    scan2_kernel<<<1, 256>>>();
    scan3_kernel<<<NSB, 512>>>();

    // h = x[:,2:130] @ gat_w        (K=128, 64 cols)
    gemm_kernel<64, 128><<<dim3(GX, 1), 128>>>(x, 130, 2, gatw, 64, 0, nullptr,
                                               (float*)ph, 64, NN, 128, 0,
                                               nullptr, nullptr, nullptr, nullptr);
    // per-node attention logits
    alpha_kernel<<<(NN * 32 + 255) / 256, 256>>>(asrc, adst);
    // scatter edges into CSR with per-edge exp
    scatter_kernel<<<(EE + 255) / 256, 256>>>(ei);
    // softmax-normalized aggregation (no atomics)
    agg_kernel<<<(NN * 32 + 255) / 256, 256>>>();

    // fc1: relu( x3 @ fc1_w[128:192,:] + x0*u1 + x1*u2 + cc )   (K=64, 384 cols)
    gemm_kernel<128, 256><<<dim3(GX, 3), 256>>>((const float*)px3, 64, 0, fc1w, 384, 128, nullptr,
                                                (float*)ph1, 384, NN, 64, 1,
                                                x, (const float*)pu1, (const float*)pu2, (const float*)pcc);
    // fc2: relu( h1 @ fc2_w + fc2_b )                            (K=384, 128 cols)
    gemm_kernel<128, 256><<<dim3(GX, 1), 256>>>((const float*)ph1, 384, 0, fc2w, 128, 0, fc2b,
                                                (float*)ph2, 128, NN, 384, 1,
                                                nullptr, nullptr, nullptr, nullptr);
    // fc3: h2 @ fc3_w + fc3_b                                    (K=128, 64 cols)
    gemm_kernel<64, 128><<<dim3(GX, 1), 128>>>((const float*)ph2, 128, 0, fc3w, 64, 0, fc3b,
                                               out, 64, NN, 128, 0,
                                               nullptr, nullptr, nullptr, nullptr);
}

// round 5
// speedup vs baseline: 1.8319x; 1.4672x over previous
#include <cuda_runtime.h>
#include <math.h>

#define NN 100000
#define EE 1600000
#define NSB ((NN + 511) / 512)   // 196 scan blocks

// ---------------- scratch (device globals; no allocation allowed) ------------
__device__ float g_h  [(size_t)NN * 64];    // GAT h = x[:,2:] @ gat_w
__device__ float g_x3 [(size_t)NN * 64];    // aggregated GAT output (pre-bias)
__device__ float g_h1 [(size_t)NN * 384];   // fc1 activation
__device__ float g_h2 [(size_t)NN * 128];   // fc2 activation
__device__ float g_as [NN];
__device__ float g_ad [NN];
__device__ int   g_cnt[NN];                 // in-degree
__device__ int   g_off[NN];                 // CSR row offsets (exclusive scan)
__device__ int   g_pos[NN];                 // scatter cursors
__device__ int   g_srcs[EE];                // CSR src indices
__device__ float g_exs [EE];                // per-edge exp(leakyrelu(...))
__device__ int   g_bsum[NSB], g_boff[NSB];
__device__ float g_u1[384], g_u2[384], g_cc[384];
__device__ int   g_is64;

// ---------------- int32/int64 edge-index detection ---------------------------
__global__ void detect_kernel(const unsigned* __restrict__ p) {
    __shared__ unsigned sh[256];
    sh[threadIdx.x] = p[2 * threadIdx.x + 1];
    __syncthreads();
    if (threadIdx.x == 0) {
        unsigned o = 0;
        for (int i = 0; i < 256; i++) o |= sh[i];
        g_is64 = (o == 0) ? 1 : 0;
    }
}

// ---------------- precompute rank-2 epilogue vectors for fc1 -----------------
__global__ void prep_kernel(const float* __restrict__ w1, const float* __restrict__ b1,
                            const float* __restrict__ w2, const float* __restrict__ b2,
                            const float* __restrict__ gatb,
                            const float* __restrict__ fc1w, const float* __restrict__ fc1b) {
    int k = threadIdx.x;  // 384 threads
    float s1 = 0.f, s2 = 0.f, c = fc1b[k];
    for (int j = 0; j < 64; j++) {
        float wa = fc1w[(size_t)j * 384 + k];
        float wb = fc1w[(size_t)(64 + j) * 384 + k];
        float wc = fc1w[(size_t)(128 + j) * 384 + k];
        s1 += w1[j] * wa;
        s2 += w2[j] * wb;
        c  += b1[j] * wa + b2[j] * wb + gatb[j] * wc;
    }
    g_u1[k] = s1; g_u2[k] = s2; g_cc[k] = c;
}

__global__ void zero_cnt_kernel() {
    int i = blockIdx.x * blockDim.x + threadIdx.x;
    if (i < NN) g_cnt[i] = 0;
}

// ---------------- degree histogram -------------------------------------------
__global__ void hist_kernel(const void* __restrict__ idx) {
    int e = blockIdx.x * blockDim.x + threadIdx.x;
    if (e >= EE) return;
    int d = g_is64 ? (int)((const long long*)idx)[EE + e]
                   : ((const int*)idx)[EE + e];
    atomicAdd(&g_cnt[d], 1);
}

// ---------------- 3-kernel exclusive scan over g_cnt -------------------------
__global__ void scan1_kernel() {               // grid NSB, 256 thr
    __shared__ int sh[256];
    int b = blockIdx.x, t = threadIdx.x;
    int i0 = b * 512 + t;
    int v = 0;
    if (i0 < NN) v += g_cnt[i0];
    if (i0 + 256 < NN) v += g_cnt[i0 + 256];
    sh[t] = v; __syncthreads();
    for (int o = 128; o; o >>= 1) { if (t < o) sh[t] += sh[t + o]; __syncthreads(); }
    if (t == 0) g_bsum[b] = sh[0];
}

__global__ void scan2_kernel() {               // 1 block, 256 thr (NSB <= 256)
    __shared__ int sh[256];
    int t = threadIdx.x;
    int v = (t < NSB) ? g_bsum[t] : 0;
    sh[t] = v;
    for (int o = 1; o < 256; o <<= 1) {
        __syncthreads();
        int u = (t >= o) ? sh[t - o] : 0;
        __syncthreads();
        sh[t] += u;
    }
    __syncthreads();
    if (t < NSB) g_boff[t] = sh[t] - v;        // exclusive
}

__global__ void scan3_kernel() {               // grid NSB, 512 thr
    __shared__ int sh[512];
    int b = blockIdx.x, t = threadIdx.x;
    int i = b * 512 + t;
    int c = (i < NN) ? g_cnt[i] : 0;
    sh[t] = c;
    for (int o = 1; o < 512; o <<= 1) {
        __syncthreads();
        int u = (t >= o) ? sh[t - o] : 0;
        __syncthreads();
        sh[t] += u;
    }
    __syncthreads();
    if (i < NN) {
        int excl = sh[t] - c + g_boff[b];
        g_off[i] = excl;
        g_pos[i] = excl;
    }
}

// ---------------- alpha_src / alpha_dst per node (warp per node) -------------
__global__ void alpha_kernel(const float* __restrict__ asrc, const float* __restrict__ adst) {
    int gw = (int)((blockIdx.x * blockDim.x + threadIdx.x) >> 5);
    int lane = threadIdx.x & 31;
    if (gw >= NN) return;
    float h0 = g_h[(size_t)gw * 64 + lane];
    float h1 = g_h[(size_t)gw * 64 + 32 + lane];
    float s = h0 * asrc[lane] + h1 * asrc[32 + lane];
    float d = h0 * adst[lane] + h1 * adst[32 + lane];
#pragma unroll
    for (int o = 16; o; o >>= 1) {
        s += __shfl_xor_sync(0xffffffffu, s, o);
        d += __shfl_xor_sync(0xffffffffu, d, o);
    }
    if (lane == 0) { g_as[gw] = s; g_ad[gw] = d; }
}

// ---------------- scatter into CSR + per-edge exp ----------------------------
__global__ void scatter_kernel(const void* __restrict__ idx) {
    int e = blockIdx.x * blockDim.x + threadIdx.x;
    if (e >= EE) return;
    int s, d;
    if (g_is64) {
        const long long* q = (const long long*)idx;
        s = (int)q[e]; d = (int)q[EE + e];
    } else {
        const int* q = (const int*)idx;
        s = q[e]; d = q[EE + e];
    }
    float v = g_as[s] + g_ad[d];
    v = (v > 0.f) ? v : 0.2f * v;
    float ex = expf(v);
    int p = atomicAdd(&g_pos[d], 1);
    g_srcs[p] = s;
    g_exs[p] = ex;
}

// ---------------- CSR aggregation: warp per destination node -----------------
__global__ void agg_kernel() {
    int node = (int)((blockIdx.x * (size_t)blockDim.x + threadIdx.x) >> 5);
    int lane = threadIdx.x & 31;
    if (node >= NN) return;
    int beg = g_off[node];
    int cnt = g_cnt[node];
    float v = g_as[node] + g_ad[node];
    v = (v > 0.f) ? v : 0.2f * v;
    float ex_self = expf(v);
    float dsum = 0.f;
    for (int i = lane; i < cnt; i += 32) dsum += g_exs[beg + i];
#pragma unroll
    for (int o = 16; o; o >>= 1) dsum += __shfl_xor_sync(0xffffffffu, dsum, o);
    float invd = 1.f / (dsum + ex_self + 1e-16f);
    float2 acc;
    {
        float2 hv = *(const float2*)(g_h + (size_t)node * 64 + lane * 2);
        float c = ex_self * invd;
        acc.x = c * hv.x; acc.y = c * hv.y;
    }
#pragma unroll 4
    for (int e = 0; e < cnt; e++) {
        int s = g_srcs[beg + e];
        float c = g_exs[beg + e] * invd;
        float2 hv = *(const float2*)(g_h + (size_t)s * 64 + lane * 2);
        acc.x += c * hv.x; acc.y += c * hv.y;
    }
    *(float2*)(g_x3 + (size_t)node * 64 + lane * 2) = acc;
}

// ---------------- fp32 SIMT GEMM (accuracy-critical paths) -------------------
template<int BN, int NTHR>
__global__ void __launch_bounds__(NTHR)
gemm_kernel(const float* __restrict__ A, int lda, int acol,
            const float* __restrict__ W, int ldw, int wrow0,
            const float* __restrict__ bias,
            float* __restrict__ C, int ldc,
            int n, int K, int do_relu) {
    constexpr int BM = 128, BK = 16;
    __shared__ float As[BK][BM + 4];
    __shared__ float Ws[BK][BN];
    const int tid = threadIdx.x;
    const int tx = tid % (BN / 8);
    const int ty = tid / (BN / 8);
    const int row0 = blockIdx.x * BM;
    const int col0 = blockIdx.y * BN;
    float acc[8][8] = {};

    for (int kk = 0; kk < K; kk += BK) {
#pragma unroll
        for (int l = 0; l < (BM * BK) / NTHR; l++) {
            int i = tid + l * NTHR;
            int c = i & (BK - 1), r = i >> 4;
            int gr = row0 + r;
            As[c][r] = (gr < n) ? A[(size_t)gr * lda + acol + kk + c] : 0.f;
        }
#pragma unroll
        for (int l = 0; l < (BK * BN / 4) / NTHR; l++) {
            int i = tid + l * NTHR;
            int r = i / (BN / 4), c4 = i % (BN / 4);
            *(float4*)&Ws[r][c4 * 4] =
                *(const float4*)&W[(size_t)(wrow0 + kk + r) * ldw + col0 + c4 * 4];
        }
        __syncthreads();
#pragma unroll
        for (int k = 0; k < BK; k++) {
            float a[8], b[8];
            *(float4*)&a[0] = *(const float4*)&As[k][ty * 8];
            *(float4*)&a[4] = *(const float4*)&As[k][ty * 8 + 4];
            *(float4*)&b[0] = *(const float4*)&Ws[k][tx * 8];
            *(float4*)&b[4] = *(const float4*)&Ws[k][tx * 8 + 4];
#pragma unroll
            for (int i = 0; i < 8; i++)
#pragma unroll
                for (int j = 0; j < 8; j++)
                    acc[i][j] += a[i] * b[j];
        }
        __syncthreads();
    }

    float bj[8];
#pragma unroll
    for (int j = 0; j < 8; j++) bj[j] = bias ? bias[col0 + tx * 8 + j] : 0.f;
#pragma unroll
    for (int i = 0; i < 8; i++) {
        int r = row0 + ty * 8 + i;
        if (r >= n) continue;
        float v[8];
#pragma unroll
        for (int j = 0; j < 8; j++) {
            float t = acc[i][j] + bj[j];
            if (do_relu) t = fmaxf(t, 0.f);
            v[j] = t;
        }
        float* cp = &C[(size_t)r * ldc + col0 + tx * 8];
        *(float4*)cp       = make_float4(v[0], v[1], v[2], v[3]);
        *(float4*)(cp + 4) = make_float4(v[4], v[5], v[6], v[7]);
    }
}

// ---------------- TF32 tensor-core GEMM (fc1 / fc2) ---------------------------
__device__ __forceinline__ unsigned f2tf(float x) {
    unsigned r; asm("cvt.rna.tf32.f32 %0, %1;" : "=r"(r) : "f"(x)); return r;
}
__device__ __forceinline__ void mma_tf32(float* d, const unsigned* a, const unsigned* b) {
    asm volatile(
        "mma.sync.aligned.m16n8k8.row.col.f32.tf32.tf32.f32 "
        "{%0,%1,%2,%3}, {%4,%5,%6,%7}, {%8,%9}, {%0,%1,%2,%3};\n"
        : "+f"(d[0]), "+f"(d[1]), "+f"(d[2]), "+f"(d[3])
        : "r"(a[0]), "r"(a[1]), "r"(a[2]), "r"(a[3]), "r"(b[0]), "r"(b[1]));
}

// BM=128, BK=32. BN=128 -> 8 warps (2m x 4n); BN=64 -> 4 warps (2m x 2n).
// Warp tile 64x32: 4 m-frags x 4 n-frags of m16n8k8.
template<int BN>
__global__ void __launch_bounds__(BN == 128 ? 256 : 128)
tf32_gemm(const float* __restrict__ A, int lda,
          const float* __restrict__ W, int ldw, int wrow0,
          const float* __restrict__ bias,
          float* __restrict__ C, int ldc,
          int n, int K, int do_relu,
          const float* __restrict__ xr,
          const float* __restrict__ u1,
          const float* __restrict__ u2,
          const float* __restrict__ cc) {
    constexpr int BM = 128, BK = 32;
    constexpr int WN_N = BN / 32;               // warps along n
    constexpr int NT = WN_N * 2 * 32;           // threads
    constexpr int BSTR = BN + 8;                // ≡ 8 (mod 32): conflict-free frag reads
    __shared__ unsigned As[BM][BK + 4];         // stride 36 ≡ 4 (mod 32)
    __shared__ unsigned Bs[BK][BSTR];

    const int tid = threadIdx.x;
    const int warp = tid >> 5, lane = tid & 31;
    const int wm = warp / WN_N;                 // 0..1
    const int wn = warp % WN_N;
    const int grp = lane >> 2, qid = lane & 3;
    const int row0 = blockIdx.x * BM;
    const int col0 = blockIdx.y * BN;

    float acc[4][4][4] = {};                    // [mf][nf][reg]

    for (int kk = 0; kk < K; kk += BK) {
        // A tile: 128x32 floats, float4 loads, tf32-convert into smem
#pragma unroll
        for (int l = 0; l < (BM * BK / 4) / NT; l++) {
            int i = tid + l * NT;
            int r = i >> 3, c4 = (i & 7) * 4;
            float4 v = (row0 + r < n)
                ? *(const float4*)&A[(size_t)(row0 + r) * lda + kk + c4]
                : make_float4(0.f, 0.f, 0.f, 0.f);
            As[r][c4 + 0] = f2tf(v.x); As[r][c4 + 1] = f2tf(v.y);
            As[r][c4 + 2] = f2tf(v.z); As[r][c4 + 3] = f2tf(v.w);
        }
        // B tile: 32xBN floats, k-major in smem
#pragma unroll
        for (int l = 0; l < (BK * BN / 4) / NT; l++) {
            int i = tid + l * NT;
            int r = i / (BN / 4), c4 = (i % (BN / 4)) * 4;
            float4 v = *(const float4*)&W[(size_t)(wrow0 + kk + r) * ldw + col0 + c4];
            Bs[r][c4 + 0] = f2tf(v.x); Bs[r][c4 + 1] = f2tf(v.y);
            Bs[r][c4 + 2] = f2tf(v.z); Bs[r][c4 + 3] = f2tf(v.w);
        }
        __syncthreads();
#pragma unroll
        for (int ks = 0; ks < BK / 8; ks++) {
            const int k0 = ks * 8;
            unsigned a[4][4], b[4][2];
#pragma unroll
            for (int mf = 0; mf < 4; mf++) {
                int r = wm * 64 + mf * 16 + grp;
                a[mf][0] = As[r][k0 + qid];
                a[mf][1] = As[r + 8][k0 + qid];
                a[mf][2] = As[r][k0 + qid + 4];
                a[mf][3] = As[r + 8][k0 + qid + 4];
            }
#pragma unroll
            for (int nf = 0; nf < 4; nf++) {
                int c = wn * 32 + nf * 8 + grp;
                b[nf][0] = Bs[k0 + qid][c];
                b[nf][1] = Bs[k0 + qid + 4][c];
            }
#pragma unroll
            for (int mf = 0; mf < 4; mf++)
#pragma unroll
                for (int nf = 0; nf < 4; nf++)
                    mma_tf32(acc[mf][nf], a[mf], b[nf]);
        }
        __syncthreads();
    }

    // epilogue: bias / rank-2(x0,x1) / relu, float2 stores
#pragma unroll
    for (int mf = 0; mf < 4; mf++) {
#pragma unroll
        for (int half = 0; half < 2; half++) {
            int r = row0 + wm * 64 + mf * 16 + grp + half * 8;
            if (r >= n) continue;
            float xa = 0.f, xb = 0.f;
            if (xr) { xa = xr[(size_t)r * 130]; xb = xr[(size_t)r * 130 + 1]; }
#pragma unroll
            for (int nf = 0; nf < 4; nf++) {
                int c = col0 + wn * 32 + nf * 8 + qid * 2;
                float v0 = acc[mf][nf][half * 2 + 0];
                float v1 = acc[mf][nf][half * 2 + 1];
                if (bias) { v0 += bias[c]; v1 += bias[c + 1]; }
                if (xr) {
                    v0 += xa * u1[c]     + xb * u2[c]     + cc[c];
                    v1 += xa * u1[c + 1] + xb * u2[c + 1] + cc[c + 1];
                }
                if (do_relu) { v0 = fmaxf(v0, 0.f); v1 = fmaxf(v1, 0.f); }
                *(float2*)&C[(size_t)r * ldc + c] = make_float2(v0, v1);
            }
        }
    }
}

// -----------------------------------------------------------------------------
extern "C" void kernel_launch(void* const* d_in, const int* in_sizes, int n_in,
                              void* d_out, int out_size) {
    const float* x    = (const float*)d_in[0];
    const void*  ei   = d_in[1];
    const float* w1   = (const float*)d_in[2];
    const float* b1   = (const float*)d_in[3];
    const float* w2   = (const float*)d_in[4];
    const float* b2   = (const float*)d_in[5];
    const float* gatw = (const float*)d_in[6];
    const float* asrc = (const float*)d_in[7];
    const float* adst = (const float*)d_in[8];
    const float* gatb = (const float*)d_in[9];
    const float* fc1w = (const float*)d_in[10];
    const float* fc1b = (const float*)d_in[11];
    const float* fc2w = (const float*)d_in[12];
    const float* fc2b = (const float*)d_in[13];
    const float* fc3w = (const float*)d_in[14];
    const float* fc3b = (const float*)d_in[15];
    float* out = (float*)d_out;

    void *ph, *px3, *ph1, *ph2, *pu1, *pu2, *pcc;
    cudaGetSymbolAddress(&ph,  g_h);
    cudaGetSymbolAddress(&px3, g_x3);
    cudaGetSymbolAddress(&ph1, g_h1);
    cudaGetSymbolAddress(&ph2, g_h2);
    cudaGetSymbolAddress(&pu1, g_u1);
    cudaGetSymbolAddress(&pu2, g_u2);
    cudaGetSymbolAddress(&pcc, g_cc);

    const int GX = (NN + 127) / 128;   // 782

    detect_kernel<<<1, 256>>>((const unsigned*)ei);
    prep_kernel<<<1, 384>>>(w1, b1, w2, b2, gatb, fc1w, fc1b);
    zero_cnt_kernel<<<(NN + 255) / 256, 256>>>();

    // CSR build
    hist_kernel<<<(EE + 255) / 256, 256>>>(ei);
    scan1_kernel<<<NSB, 256>>>();
    scan2_kernel<<<1, 256>>>();
    scan3_kernel<<<NSB, 512>>>();

    // h = x[:,2:130] @ gat_w  (fp32: feeds exp(), keep exact)
    gemm_kernel<64, 128><<<dim3(GX, 1), 128>>>(x, 130, 2, gatw, 64, 0, nullptr,
                                               (float*)ph, 64, NN, 128, 0);
    alpha_kernel<<<(NN * 32 + 255) / 256, 256>>>(asrc, adst);
    scatter_kernel<<<(EE + 255) / 256, 256>>>(ei);
    agg_kernel<<<(NN * 32 + 255) / 256, 256>>>();

    // fc1 (TF32): relu( x3 @ fc1_w[128:192,:] + x0*u1 + x1*u2 + cc )
    tf32_gemm<128><<<dim3(GX, 3), 256>>>((const float*)px3, 64, fc1w, 384, 128, nullptr,
                                         (float*)ph1, 384, NN, 64, 1,
                                         x, (const float*)pu1, (const float*)pu2, (const float*)pcc);
    // fc2 (TF32): relu( h1 @ fc2_w + fc2_b )
    tf32_gemm<128><<<dim3(GX, 1), 256>>>((const float*)ph1, 384, fc2w, 128, 0, fc2b,
                                         (float*)ph2, 128, NN, 384, 1,
                                         nullptr, nullptr, nullptr, nullptr);
    // fc3 (fp32, final output): h2 @ fc3_w + fc3_b
    gemm_kernel<64, 128><<<dim3(GX, 1), 128>>>((const float*)ph2, 128, 0, fc3w, 64, 0, fc3b,
                                               out, 64, NN, 128, 0);
}

// round 6
// speedup vs baseline: 1.9485x; 1.0637x over previous
#include <cuda_runtime.h>
#include <math.h>

#define NN 100000
#define EE 1600000
#define NSB ((NN + 511) / 512)   // 196 scan blocks

// ---------------- scratch (device globals; no allocation allowed) ------------
__device__ float g_h  [(size_t)NN * 64];    // GAT h = x[:,2:] @ gat_w
__device__ float g_x3 [(size_t)NN * 64];    // aggregated GAT output (pre-bias)
__device__ float g_h1 [(size_t)NN * 384];   // fc1 activation
__device__ float g_h2 [(size_t)NN * 128];   // fc2 activation
__device__ float g_as [NN];
__device__ float g_ad [NN];
__device__ int   g_cnt[NN];                 // in-degree
__device__ int   g_off[NN];                 // CSR row offsets (exclusive scan)
__device__ int   g_pos[NN];                 // scatter cursors
__device__ int   g_srcs[EE];                // CSR src indices
__device__ float g_exs [EE];                // per-edge exp(leakyrelu(...))
__device__ int   g_bsum[NSB], g_boff[NSB];
__device__ float g_u1[384], g_u2[384], g_cc[384];
__device__ int   g_is64;

// ---------------- int32/int64 edge-index detection ---------------------------
__global__ void detect_kernel(const unsigned* __restrict__ p) {
    __shared__ unsigned sh[256];
    sh[threadIdx.x] = p[2 * threadIdx.x + 1];
    __syncthreads();
    if (threadIdx.x == 0) {
        unsigned o = 0;
        for (int i = 0; i < 256; i++) o |= sh[i];
        g_is64 = (o == 0) ? 1 : 0;
    }
}

// ---------------- precompute rank-2 epilogue vectors for fc1 -----------------
__global__ void prep_kernel(const float* __restrict__ w1, const float* __restrict__ b1,
                            const float* __restrict__ w2, const float* __restrict__ b2,
                            const float* __restrict__ gatb,
                            const float* __restrict__ fc1w, const float* __restrict__ fc1b) {
    int k = threadIdx.x;  // 384 threads
    float s1 = 0.f, s2 = 0.f, c = fc1b[k];
    for (int j = 0; j < 64; j++) {
        float wa = fc1w[(size_t)j * 384 + k];
        float wb = fc1w[(size_t)(64 + j) * 384 + k];
        float wc = fc1w[(size_t)(128 + j) * 384 + k];
        s1 += w1[j] * wa;
        s2 += w2[j] * wb;
        c  += b1[j] * wa + b2[j] * wb + gatb[j] * wc;
    }
    g_u1[k] = s1; g_u2[k] = s2; g_cc[k] = c;
}

__global__ void zero_cnt_kernel() {
    int i = blockIdx.x * blockDim.x + threadIdx.x;
    if (i < NN) g_cnt[i] = 0;
}

// ---------------- degree histogram -------------------------------------------
__global__ void hist_kernel(const void* __restrict__ idx) {
    int e = blockIdx.x * blockDim.x + threadIdx.x;
    if (e >= EE) return;
    int d = g_is64 ? (int)((const long long*)idx)[EE + e]
                   : ((const int*)idx)[EE + e];
    atomicAdd(&g_cnt[d], 1);
}

// ---------------- 3-kernel exclusive scan over g_cnt -------------------------
__global__ void scan1_kernel() {               // grid NSB, 256 thr
    __shared__ int sh[256];
    int b = blockIdx.x, t = threadIdx.x;
    int i0 = b * 512 + t;
    int v = 0;
    if (i0 < NN) v += g_cnt[i0];
    if (i0 + 256 < NN) v += g_cnt[i0 + 256];
    sh[t] = v; __syncthreads();
    for (int o = 128; o; o >>= 1) { if (t < o) sh[t] += sh[t + o]; __syncthreads(); }
    if (t == 0) g_bsum[b] = sh[0];
}

__global__ void scan2_kernel() {               // 1 block, 256 thr (NSB <= 256)
    __shared__ int sh[256];
    int t = threadIdx.x;
    int v = (t < NSB) ? g_bsum[t] : 0;
    sh[t] = v;
    for (int o = 1; o < 256; o <<= 1) {
        __syncthreads();
        int u = (t >= o) ? sh[t - o] : 0;
        __syncthreads();
        sh[t] += u;
    }
    __syncthreads();
    if (t < NSB) g_boff[t] = sh[t] - v;        // exclusive
}

__global__ void scan3_kernel() {               // grid NSB, 512 thr
    __shared__ int sh[512];
    int b = blockIdx.x, t = threadIdx.x;
    int i = b * 512 + t;
    int c = (i < NN) ? g_cnt[i] : 0;
    sh[t] = c;
    for (int o = 1; o < 512; o <<= 1) {
        __syncthreads();
        int u = (t >= o) ? sh[t - o] : 0;
        __syncthreads();
        sh[t] += u;
    }
    __syncthreads();
    if (i < NN) {
        int excl = sh[t] - c + g_boff[b];
        g_off[i] = excl;
        g_pos[i] = excl;
    }
}

// ---------------- alpha_src / alpha_dst per node (warp per node) -------------
__global__ void alpha_kernel(const float* __restrict__ asrc, const float* __restrict__ adst) {
    int gw = (int)((blockIdx.x * blockDim.x + threadIdx.x) >> 5);
    int lane = threadIdx.x & 31;
    if (gw >= NN) return;
    float h0 = g_h[(size_t)gw * 64 + lane];
    float h1 = g_h[(size_t)gw * 64 + 32 + lane];
    float s = h0 * asrc[lane] + h1 * asrc[32 + lane];
    float d = h0 * adst[lane] + h1 * adst[32 + lane];
#pragma unroll
    for (int o = 16; o; o >>= 1) {
        s += __shfl_xor_sync(0xffffffffu, s, o);
        d += __shfl_xor_sync(0xffffffffu, d, o);
    }
    if (lane == 0) { g_as[gw] = s; g_ad[gw] = d; }
}

// ---------------- scatter into CSR + per-edge exp ----------------------------
__global__ void scatter_kernel(const void* __restrict__ idx) {
    int e = blockIdx.x * blockDim.x + threadIdx.x;
    if (e >= EE) return;
    int s, d;
    if (g_is64) {
        const long long* q = (const long long*)idx;
        s = (int)q[e]; d = (int)q[EE + e];
    } else {
        const int* q = (const int*)idx;
        s = q[e]; d = q[EE + e];
    }
    float v = g_as[s] + g_ad[d];
    v = (v > 0.f) ? v : 0.2f * v;
    float ex = expf(v);
    int p = atomicAdd(&g_pos[d], 1);
    g_srcs[p] = s;
    g_exs[p] = ex;
}

// ---------------- CSR aggregation: warp per destination node -----------------
__global__ void agg_kernel() {
    int node = (int)((blockIdx.x * (size_t)blockDim.x + threadIdx.x) >> 5);
    int lane = threadIdx.x & 31;
    if (node >= NN) return;
    int beg = g_off[node];
    int cnt = g_cnt[node];
    float v = g_as[node] + g_ad[node];
    v = (v > 0.f) ? v : 0.2f * v;
    float ex_self = expf(v);
    float dsum = 0.f;
    for (int i = lane; i < cnt; i += 32) dsum += g_exs[beg + i];
#pragma unroll
    for (int o = 16; o; o >>= 1) dsum += __shfl_xor_sync(0xffffffffu, dsum, o);
    float invd = 1.f / (dsum + ex_self + 1e-16f);
    float2 acc;
    {
        float2 hv = *(const float2*)(g_h + (size_t)node * 64 + lane * 2);
        float c = ex_self * invd;
        acc.x = c * hv.x; acc.y = c * hv.y;
    }
#pragma unroll 4
    for (int e = 0; e < cnt; e++) {
        int s = g_srcs[beg + e];
        float c = g_exs[beg + e] * invd;
        float2 hv = *(const float2*)(g_h + (size_t)s * 64 + lane * 2);
        acc.x += c * hv.x; acc.y += c * hv.y;
    }
    *(float2*)(g_x3 + (size_t)node * 64 + lane * 2) = acc;
}

// ---------------- TF32 helpers -------------------------------------------------
__device__ __forceinline__ unsigned f2tf(float x) {
    unsigned r; asm("cvt.rna.tf32.f32 %0, %1;" : "=r"(r) : "f"(x)); return r;
}
__device__ __forceinline__ void mma_tf32(float* d, const unsigned* a, const unsigned* b) {
    asm volatile(
        "mma.sync.aligned.m16n8k8.row.col.f32.tf32.tf32.f32 "
        "{%0,%1,%2,%3}, {%4,%5,%6,%7}, {%8,%9}, {%0,%1,%2,%3};\n"
        : "+f"(d[0]), "+f"(d[1]), "+f"(d[2]), "+f"(d[3])
        : "r"(a[0]), "r"(a[1]), "r"(a[2]), "r"(a[3]), "r"(b[0]), "r"(b[1]));
}

// ---------------- plain TF32 GEMM (fc1 / fc2; error budget measured OK) -------
// BM=128, BK=32. BN=128 -> 8 warps (2m x 4n). Warp tile 64x32.
template<int BN>
__global__ void __launch_bounds__(BN == 128 ? 256 : 128)
tf32_gemm(const float* __restrict__ A, int lda,
          const float* __restrict__ W, int ldw, int wrow0,
          const float* __restrict__ bias,
          float* __restrict__ C, int ldc,
          int n, int K, int do_relu,
          const float* __restrict__ xr,
          const float* __restrict__ u1,
          const float* __restrict__ u2,
          const float* __restrict__ cc) {
    constexpr int BM = 128, BK = 32;
    constexpr int WN_N = BN / 32;
    constexpr int NT = WN_N * 2 * 32;
    constexpr int BSTR = BN + 8;
    __shared__ unsigned As[BM][BK + 4];
    __shared__ unsigned Bs[BK][BSTR];

    const int tid = threadIdx.x;
    const int warp = tid >> 5, lane = tid & 31;
    const int wm = warp / WN_N;
    const int wn = warp % WN_N;
    const int grp = lane >> 2, qid = lane & 3;
    const int row0 = blockIdx.x * BM;
    const int col0 = blockIdx.y * BN;

    float acc[4][4][4] = {};

    for (int kk = 0; kk < K; kk += BK) {
#pragma unroll
        for (int l = 0; l < (BM * BK / 4) / NT; l++) {
            int i = tid + l * NT;
            int r = i >> 3, c4 = (i & 7) * 4;
            float4 v = (row0 + r < n)
                ? *(const float4*)&A[(size_t)(row0 + r) * lda + kk + c4]
                : make_float4(0.f, 0.f, 0.f, 0.f);
            As[r][c4 + 0] = f2tf(v.x); As[r][c4 + 1] = f2tf(v.y);
            As[r][c4 + 2] = f2tf(v.z); As[r][c4 + 3] = f2tf(v.w);
        }
#pragma unroll
        for (int l = 0; l < (BK * BN / 4) / NT; l++) {
            int i = tid + l * NT;
            int r = i / (BN / 4), c4 = (i % (BN / 4)) * 4;
            float4 v = *(const float4*)&W[(size_t)(wrow0 + kk + r) * ldw + col0 + c4];
            Bs[r][c4 + 0] = f2tf(v.x); Bs[r][c4 + 1] = f2tf(v.y);
            Bs[r][c4 + 2] = f2tf(v.z); Bs[r][c4 + 3] = f2tf(v.w);
        }
        __syncthreads();
#pragma unroll
        for (int ks = 0; ks < BK / 8; ks++) {
            const int k0 = ks * 8;
            unsigned a[4][4], b[4][2];
#pragma unroll
            for (int mf = 0; mf < 4; mf++) {
                int r = wm * 64 + mf * 16 + grp;
                a[mf][0] = As[r][k0 + qid];
                a[mf][1] = As[r + 8][k0 + qid];
                a[mf][2] = As[r][k0 + qid + 4];
                a[mf][3] = As[r + 8][k0 + qid + 4];
            }
#pragma unroll
            for (int nf = 0; nf < 4; nf++) {
                int c = wn * 32 + nf * 8 + grp;
                b[nf][0] = Bs[k0 + qid][c];
                b[nf][1] = Bs[k0 + qid + 4][c];
            }
#pragma unroll
            for (int mf = 0; mf < 4; mf++)
#pragma unroll
                for (int nf = 0; nf < 4; nf++)
                    mma_tf32(acc[mf][nf], a[mf], b[nf]);
        }
        __syncthreads();
    }

#pragma unroll
    for (int mf = 0; mf < 4; mf++) {
#pragma unroll
        for (int half = 0; half < 2; half++) {
            int r = row0 + wm * 64 + mf * 16 + grp + half * 8;
            if (r >= n) continue;
            float xa = 0.f, xb = 0.f;
            if (xr) { xa = xr[(size_t)r * 130]; xb = xr[(size_t)r * 130 + 1]; }
#pragma unroll
            for (int nf = 0; nf < 4; nf++) {
                int c = col0 + wn * 32 + nf * 8 + qid * 2;
                float v0 = acc[mf][nf][half * 2 + 0];
                float v1 = acc[mf][nf][half * 2 + 1];
                if (bias) { v0 += bias[c]; v1 += bias[c + 1]; }
                if (xr) {
                    v0 += xa * u1[c]     + xb * u2[c]     + cc[c];
                    v1 += xa * u1[c + 1] + xb * u2[c + 1] + cc[c + 1];
                }
                if (do_relu) { v0 = fmaxf(v0, 0.f); v1 = fmaxf(v1, 0.f); }
                *(float2*)&C[(size_t)r * ldc + c] = make_float2(v0, v1);
            }
        }
    }
}

// ---------------- split-precision 3xTF32 GEMM (fp32-accurate) ----------------
// For accuracy-critical paths: h = x[:,2:]@gat_w (feeds exp) and fc3 (output).
// x = hi + lo with hi=tf32(x), lo=tf32(x-hi); acc += hi*hi + hi*lo + lo*hi.
// BN=64, BM=128, BK=32, 128 threads (2m x 2n warps), warp tile 64x32.
// A loads use float2 (A may be only 8B-aligned, e.g. lda=130 col offset 2).
__global__ void __launch_bounds__(128)
tf32s_gemm(const float* __restrict__ A, int lda,
           const float* __restrict__ W, int ldw,
           const float* __restrict__ bias,
           float* __restrict__ C, int ldc,
           int n, int K) {
    constexpr int BM = 128, BK = 32, BN = 64;
    constexpr int NT = 128;
    constexpr int BSTR = BN + 8;
    __shared__ unsigned Ah[BM][BK + 4];
    __shared__ unsigned Al[BM][BK + 4];
    __shared__ unsigned Bh[BK][BSTR];
    __shared__ unsigned Bl[BK][BSTR];

    const int tid = threadIdx.x;
    const int warp = tid >> 5, lane = tid & 31;
    const int wm = warp >> 1;        // 0..1
    const int wn = warp & 1;         // 0..1
    const int grp = lane >> 2, qid = lane & 3;
    const int row0 = blockIdx.x * BM;
    const int col0 = blockIdx.y * BN;

    float acc[4][4][4] = {};

    for (int kk = 0; kk < K; kk += BK) {
        // A tile via float2 (8B alignment guaranteed)
#pragma unroll
        for (int l = 0; l < (BM * BK / 2) / NT; l++) {
            int i = tid + l * NT;
            int r = i >> 4, c2 = (i & 15) * 2;
            float2 v = (row0 + r < n)
                ? *(const float2*)&A[(size_t)(row0 + r) * lda + kk + c2]
                : make_float2(0.f, 0.f);
            unsigned hx = f2tf(v.x), hy = f2tf(v.y);
            Ah[r][c2]     = hx;
            Ah[r][c2 + 1] = hy;
            Al[r][c2]     = f2tf(v.x - __uint_as_float(hx));
            Al[r][c2 + 1] = f2tf(v.y - __uint_as_float(hy));
        }
        // B tile via float4
#pragma unroll
        for (int l = 0; l < (BK * BN / 4) / NT; l++) {
            int i = tid + l * NT;
            int r = i / (BN / 4), c4 = (i % (BN / 4)) * 4;
            float4 v = *(const float4*)&W[(size_t)(kk + r) * ldw + col0 + c4];
            unsigned h0 = f2tf(v.x), h1 = f2tf(v.y), h2 = f2tf(v.z), h3 = f2tf(v.w);
            Bh[r][c4 + 0] = h0; Bh[r][c4 + 1] = h1;
            Bh[r][c4 + 2] = h2; Bh[r][c4 + 3] = h3;
            Bl[r][c4 + 0] = f2tf(v.x - __uint_as_float(h0));
            Bl[r][c4 + 1] = f2tf(v.y - __uint_as_float(h1));
            Bl[r][c4 + 2] = f2tf(v.z - __uint_as_float(h2));
            Bl[r][c4 + 3] = f2tf(v.w - __uint_as_float(h3));
        }
        __syncthreads();
#pragma unroll
        for (int ks = 0; ks < BK / 8; ks++) {
            const int k0 = ks * 8;
            unsigned ah[4][4], al[4][4], bh[4][2], bl[4][2];
#pragma unroll
            for (int mf = 0; mf < 4; mf++) {
                int r = wm * 64 + mf * 16 + grp;
                ah[mf][0] = Ah[r][k0 + qid];     al[mf][0] = Al[r][k0 + qid];
                ah[mf][1] = Ah[r + 8][k0 + qid]; al[mf][1] = Al[r + 8][k0 + qid];
                ah[mf][2] = Ah[r][k0 + qid + 4]; al[mf][2] = Al[r][k0 + qid + 4];
                ah[mf][3] = Ah[r + 8][k0 + qid + 4]; al[mf][3] = Al[r + 8][k0 + qid + 4];
            }
#pragma unroll
            for (int nf = 0; nf < 4; nf++) {
                int c = wn * 32 + nf * 8 + grp;
                bh[nf][0] = Bh[k0 + qid][c];     bl[nf][0] = Bl[k0 + qid][c];
                bh[nf][1] = Bh[k0 + qid + 4][c]; bl[nf][1] = Bl[k0 + qid + 4][c];
            }
#pragma unroll
            for (int mf = 0; mf < 4; mf++)
#pragma unroll
                for (int nf = 0; nf < 4; nf++) {
                    mma_tf32(acc[mf][nf], al[mf], bh[nf]);
                    mma_tf32(acc[mf][nf], ah[mf], bl[nf]);
                    mma_tf32(acc[mf][nf], ah[mf], bh[nf]);
                }
        }
        __syncthreads();
    }

#pragma unroll
    for (int mf = 0; mf < 4; mf++) {
#pragma unroll
        for (int half = 0; half < 2; half++) {
            int r = row0 + wm * 64 + mf * 16 + grp + half * 8;
            if (r >= n) continue;
#pragma unroll
            for (int nf = 0; nf < 4; nf++) {
                int c = col0 + wn * 32 + nf * 8 + qid * 2;
                float v0 = acc[mf][nf][half * 2 + 0];
                float v1 = acc[mf][nf][half * 2 + 1];
                if (bias) { v0 += bias[c]; v1 += bias[c + 1]; }
                *(float2*)&C[(size_t)r * ldc + c] = make_float2(v0, v1);
            }
        }
    }
}

// -----------------------------------------------------------------------------
extern "C" void kernel_launch(void* const* d_in, const int* in_sizes, int n_in,
                              void* d_out, int out_size) {
    const float* x    = (const float*)d_in[0];
    const void*  ei   = d_in[1];
    const float* w1   = (const float*)d_in[2];
    const float* b1   = (const float*)d_in[3];
    const float* w2   = (const float*)d_in[4];
    const float* b2   = (const float*)d_in[5];
    const float* gatw = (const float*)d_in[6];
    const float* asrc = (const float*)d_in[7];
    const float* adst = (const float*)d_in[8];
    const float* gatb = (const float*)d_in[9];
    const float* fc1w = (const float*)d_in[10];
    const float* fc1b = (const float*)d_in[11];
    const float* fc2w = (const float*)d_in[12];
    const float* fc2b = (const float*)d_in[13];
    const float* fc3w = (const float*)d_in[14];
    const float* fc3b = (const float*)d_in[15];
    float* out = (float*)d_out;

    void *ph, *px3, *ph1, *ph2, *pu1, *pu2, *pcc;
    cudaGetSymbolAddress(&ph,  g_h);
    cudaGetSymbolAddress(&px3, g_x3);
    cudaGetSymbolAddress(&ph1, g_h1);
    cudaGetSymbolAddress(&ph2, g_h2);
    cudaGetSymbolAddress(&pu1, g_u1);
    cudaGetSymbolAddress(&pu2, g_u2);
    cudaGetSymbolAddress(&pcc, g_cc);

    const int GX = (NN + 127) / 128;   // 782

    detect_kernel<<<1, 256>>>((const unsigned*)ei);
    prep_kernel<<<1, 384>>>(w1, b1, w2, b2, gatb, fc1w, fc1b);
    zero_cnt_kernel<<<(NN + 255) / 256, 256>>>();

    // CSR build
    hist_kernel<<<(EE + 255) / 256, 256>>>(ei);
    scan1_kernel<<<NSB, 256>>>();
    scan2_kernel<<<1, 256>>>();
    scan3_kernel<<<NSB, 512>>>();

    // h = x[:,2:130] @ gat_w  (split 3xTF32: fp32-accurate, feeds exp)
    tf32s_gemm<<<dim3(GX, 1), 128>>>(x + 2, 130, gatw, 64, nullptr,
                                     (float*)ph, 64, NN, 128);
    alpha_kernel<<<(NN * 32 + 255) / 256, 256>>>(asrc, adst);
    scatter_kernel<<<(EE + 255) / 256, 256>>>(ei);
    agg_kernel<<<(NN * 32 + 255) / 256, 256>>>();

    // fc1 (TF32): relu( x3 @ fc1_w[128:192,:] + x0*u1 + x1*u2 + cc )
    tf32_gemm<128><<<dim3(GX, 3), 256>>>((const float*)px3, 64, fc1w, 384, 128, nullptr,
                                         (float*)ph1, 384, NN, 64, 1,
                                         x, (const float*)pu1, (const float*)pu2, (const float*)pcc);
    // fc2 (TF32): relu( h1 @ fc2_w + fc2_b )
    tf32_gemm<128><<<dim3(GX, 1), 256>>>((const float*)ph1, 384, fc2w, 128, 0, fc2b,
                                         (float*)ph2, 128, NN, 384, 1,
                                         nullptr, nullptr, nullptr, nullptr);
    // fc3 (split 3xTF32, final output): h2 @ fc3_w + fc3_b
    tf32s_gemm<<<dim3(GX, 1), 128>>>((const float*)ph2, 128, fc3w, 64, fc3b,
                                     out, 64, NN, 128);
}

// round 7
// speedup vs baseline: 1.9495x; 1.0005x over previous
#include <cuda_runtime.h>
#include <math.h>

#define NN 100000
#define EE 1600000
#define NSB ((NN + 511) / 512)   // 196 scan blocks

// ---------------- scratch (device globals; no allocation allowed) ------------
__device__ float g_h  [(size_t)NN * 64];    // GAT h = x[:,2:] @ gat_w
__device__ float g_x3 [(size_t)NN * 64];    // aggregated GAT output (pre-bias)
__device__ float g_h1 [(size_t)NN * 384];   // fc1 activation
__device__ float g_h2 [(size_t)NN * 128];   // fc2 activation
__device__ float g_as [NN];
__device__ float g_ad [NN];
__device__ int   g_cnt[NN];                 // in-degree
__device__ int   g_off[NN];                 // CSR row offsets (exclusive scan)
__device__ int   g_pos[NN];                 // scatter cursors
__device__ int   g_srcs[EE];                // CSR src indices
__device__ float g_exs [EE];                // per-edge exp(leakyrelu(...))
__device__ int   g_bsum[NSB], g_boff[NSB];
__device__ float g_u1[384], g_u2[384], g_cc[384];
__device__ int   g_is64;

// ---------------- int32/int64 edge-index detection ---------------------------
__global__ void detect_kernel(const unsigned* __restrict__ p) {
    __shared__ unsigned sh[256];
    sh[threadIdx.x] = p[2 * threadIdx.x + 1];
    __syncthreads();
    if (threadIdx.x == 0) {
        unsigned o = 0;
        for (int i = 0; i < 256; i++) o |= sh[i];
        g_is64 = (o == 0) ? 1 : 0;
    }
}

// ---------------- precompute rank-2 epilogue vectors for fc1 -----------------
__global__ void prep_kernel(const float* __restrict__ w1, const float* __restrict__ b1,
                            const float* __restrict__ w2, const float* __restrict__ b2,
                            const float* __restrict__ gatb,
                            const float* __restrict__ fc1w, const float* __restrict__ fc1b) {
    int k = threadIdx.x;  // 384 threads
    float s1 = 0.f, s2 = 0.f, c = fc1b[k];
    for (int j = 0; j < 64; j++) {
        float wa = fc1w[(size_t)j * 384 + k];
        float wb = fc1w[(size_t)(64 + j) * 384 + k];
        float wc = fc1w[(size_t)(128 + j) * 384 + k];
        s1 += w1[j] * wa;
        s2 += w2[j] * wb;
        c  += b1[j] * wa + b2[j] * wb + gatb[j] * wc;
    }
    g_u1[k] = s1; g_u2[k] = s2; g_cc[k] = c;
}

__global__ void zero_cnt_kernel() {
    int i = blockIdx.x * blockDim.x + threadIdx.x;
    if (i < NN) g_cnt[i] = 0;
}

// ---------------- degree histogram -------------------------------------------
__global__ void hist_kernel(const void* __restrict__ idx) {
    int e = blockIdx.x * blockDim.x + threadIdx.x;
    if (e >= EE) return;
    int d = g_is64 ? (int)((const long long*)idx)[EE + e]
                   : ((const int*)idx)[EE + e];
    atomicAdd(&g_cnt[d], 1);
}

// ---------------- 3-kernel exclusive scan over g_cnt -------------------------
__global__ void scan1_kernel() {               // grid NSB, 256 thr
    __shared__ int sh[256];
    int b = blockIdx.x, t = threadIdx.x;
    int i0 = b * 512 + t;
    int v = 0;
    if (i0 < NN) v += g_cnt[i0];
    if (i0 + 256 < NN) v += g_cnt[i0 + 256];
    sh[t] = v; __syncthreads();
    for (int o = 128; o; o >>= 1) { if (t < o) sh[t] += sh[t + o]; __syncthreads(); }
    if (t == 0) g_bsum[b] = sh[0];
}

__global__ void scan2_kernel() {               // 1 block, 256 thr (NSB <= 256)
    __shared__ int sh[256];
    int t = threadIdx.x;
    int v = (t < NSB) ? g_bsum[t] : 0;
    sh[t] = v;
    for (int o = 1; o < 256; o <<= 1) {
        __syncthreads();
        int u = (t >= o) ? sh[t - o] : 0;
        __syncthreads();
        sh[t] += u;
    }
    __syncthreads();
    if (t < NSB) g_boff[t] = sh[t] - v;        // exclusive
}

__global__ void scan3_kernel() {               // grid NSB, 512 thr
    __shared__ int sh[512];
    int b = blockIdx.x, t = threadIdx.x;
    int i = b * 512 + t;
    int c = (i < NN) ? g_cnt[i] : 0;
    sh[t] = c;
    for (int o = 1; o < 512; o <<= 1) {
        __syncthreads();
        int u = (t >= o) ? sh[t - o] : 0;
        __syncthreads();
        sh[t] += u;
    }
    __syncthreads();
    if (i < NN) {
        int excl = sh[t] - c + g_boff[b];
        g_off[i] = excl;
        g_pos[i] = excl;
    }
}

// ---------------- alpha_src / alpha_dst per node (warp per node) -------------
__global__ void alpha_kernel(const float* __restrict__ asrc, const float* __restrict__ adst) {
    int gw = (int)((blockIdx.x * blockDim.x + threadIdx.x) >> 5);
    int lane = threadIdx.x & 31;
    if (gw >= NN) return;
    float h0 = g_h[(size_t)gw * 64 + lane];
    float h1 = g_h[(size_t)gw * 64 + 32 + lane];
    float s = h0 * asrc[lane] + h1 * asrc[32 + lane];
    float d = h0 * adst[lane] + h1 * adst[32 + lane];
#pragma unroll
    for (int o = 16; o; o >>= 1) {
        s += __shfl_xor_sync(0xffffffffu, s, o);
        d += __shfl_xor_sync(0xffffffffu, d, o);
    }
    if (lane == 0) { g_as[gw] = s; g_ad[gw] = d; }
}

// ---------------- scatter into CSR + per-edge exp ----------------------------
__global__ void scatter_kernel(const void* __restrict__ idx) {
    int e = blockIdx.x * blockDim.x + threadIdx.x;
    if (e >= EE) return;
    int s, d;
    if (g_is64) {
        const long long* q = (const long long*)idx;
        s = (int)q[e]; d = (int)q[EE + e];
    } else {
        const int* q = (const int*)idx;
        s = q[e]; d = q[EE + e];
    }
    float v = g_as[s] + g_ad[d];
    v = (v > 0.f) ? v : 0.2f * v;
    float ex = expf(v);
    int p = atomicAdd(&g_pos[d], 1);
    g_srcs[p] = s;
    g_exs[p] = ex;
}

// ---------------- CSR aggregation: warp per destination node -----------------
__global__ void agg_kernel() {
    int node = (int)((blockIdx.x * (size_t)blockDim.x + threadIdx.x) >> 5);
    int lane = threadIdx.x & 31;
    if (node >= NN) return;
    int beg = g_off[node];
    int cnt = g_cnt[node];
    float v = g_as[node] + g_ad[node];
    v = (v > 0.f) ? v : 0.2f * v;
    float ex_self = expf(v);
    float dsum = 0.f;
    for (int i = lane; i < cnt; i += 32) dsum += g_exs[beg + i];
#pragma unroll
    for (int o = 16; o; o >>= 1) dsum += __shfl_xor_sync(0xffffffffu, dsum, o);
    float invd = 1.f / (dsum + ex_self + 1e-16f);
    float2 acc;
    {
        float2 hv = *(const float2*)(g_h + (size_t)node * 64 + lane * 2);
        float c = ex_self * invd;
        acc.x = c * hv.x; acc.y = c * hv.y;
    }
#pragma unroll 4
    for (int e = 0; e < cnt; e++) {
        int s = g_srcs[beg + e];
        float c = g_exs[beg + e] * invd;
        float2 hv = *(const float2*)(g_h + (size_t)s * 64 + lane * 2);
        acc.x += c * hv.x; acc.y += c * hv.y;
    }
    *(float2*)(g_x3 + (size_t)node * 64 + lane * 2) = acc;
}

// ---------------- TF32 helpers -------------------------------------------------
__device__ __forceinline__ unsigned f2tf(float x) {
    unsigned r; asm("cvt.rna.tf32.f32 %0, %1;" : "=r"(r) : "f"(x)); return r;
}
__device__ __forceinline__ void mma_tf32(float* d, const unsigned* a, const unsigned* b) {
    asm volatile(
        "mma.sync.aligned.m16n8k8.row.col.f32.tf32.tf32.f32 "
        "{%0,%1,%2,%3}, {%4,%5,%6,%7}, {%8,%9}, {%0,%1,%2,%3};\n"
        : "+f"(d[0]), "+f"(d[1]), "+f"(d[2]), "+f"(d[3])
        : "r"(a[0]), "r"(a[1]), "r"(a[2]), "r"(a[3]), "r"(b[0]), "r"(b[1]));
}

// ---------------- plain TF32 GEMM (fc1 / fc2; error budget measured OK) -------
// BM=128, BK=32. BN=128 -> 8 warps (2m x 4n). Warp tile 64x32.
template<int BN>
__global__ void __launch_bounds__(BN == 128 ? 256 : 128)
tf32_gemm(const float* __restrict__ A, int lda,
          const float* __restrict__ W, int ldw, int wrow0,
          const float* __restrict__ bias,
          float* __restrict__ C, int ldc,
          int n, int K, int do_relu,
          const float* __restrict__ xr,
          const float* __restrict__ u1,
          const float* __restrict__ u2,
          const float* __restrict__ cc) {
    constexpr int BM = 128, BK = 32;
    constexpr int WN_N = BN / 32;
    constexpr int NT = WN_N * 2 * 32;
    constexpr int BSTR = BN + 8;
    __shared__ unsigned As[BM][BK + 4];
    __shared__ unsigned Bs[BK][BSTR];

    const int tid = threadIdx.x;
    const int warp = tid >> 5, lane = tid & 31;
    const int wm = warp / WN_N;
    const int wn = warp % WN_N;
    const int grp = lane >> 2, qid = lane & 3;
    const int row0 = blockIdx.x * BM;
    const int col0 = blockIdx.y * BN;

    float acc[4][4][4] = {};

    for (int kk = 0; kk < K; kk += BK) {
#pragma unroll
        for (int l = 0; l < (BM * BK / 4) / NT; l++) {
            int i = tid + l * NT;
            int r = i >> 3, c4 = (i & 7) * 4;
            float4 v = (row0 + r < n)
                ? *(const float4*)&A[(size_t)(row0 + r) * lda + kk + c4]
                : make_float4(0.f, 0.f, 0.f, 0.f);
            As[r][c4 + 0] = f2tf(v.x); As[r][c4 + 1] = f2tf(v.y);
            As[r][c4 + 2] = f2tf(v.z); As[r][c4 + 3] = f2tf(v.w);
        }
#pragma unroll
        for (int l = 0; l < (BK * BN / 4) / NT; l++) {
            int i = tid + l * NT;
            int r = i / (BN / 4), c4 = (i % (BN / 4)) * 4;
            float4 v = *(const float4*)&W[(size_t)(wrow0 + kk + r) * ldw + col0 + c4];
            Bs[r][c4 + 0] = f2tf(v.x); Bs[r][c4 + 1] = f2tf(v.y);
            Bs[r][c4 + 2] = f2tf(v.z); Bs[r][c4 + 3] = f2tf(v.w);
        }
        __syncthreads();
#pragma unroll
        for (int ks = 0; ks < BK / 8; ks++) {
            const int k0 = ks * 8;
            unsigned a[4][4], b[4][2];
#pragma unroll
            for (int mf = 0; mf < 4; mf++) {
                int r = wm * 64 + mf * 16 + grp;
                a[mf][0] = As[r][k0 + qid];
                a[mf][1] = As[r + 8][k0 + qid];
                a[mf][2] = As[r][k0 + qid + 4];
                a[mf][3] = As[r + 8][k0 + qid + 4];
            }
#pragma unroll
            for (int nf = 0; nf < 4; nf++) {
                int c = wn * 32 + nf * 8 + grp;
                b[nf][0] = Bs[k0 + qid][c];
                b[nf][1] = Bs[k0 + qid + 4][c];
            }
#pragma unroll
            for (int mf = 0; mf < 4; mf++)
#pragma unroll
                for (int nf = 0; nf < 4; nf++)
                    mma_tf32(acc[mf][nf], a[mf], b[nf]);
        }
        __syncthreads();
    }

#pragma unroll
    for (int mf = 0; mf < 4; mf++) {
#pragma unroll
        for (int half = 0; half < 2; half++) {
            int r = row0 + wm * 64 + mf * 16 + grp + half * 8;
            if (r >= n) continue;
            float xa = 0.f, xb = 0.f;
            if (xr) { xa = xr[(size_t)r * 130]; xb = xr[(size_t)r * 130 + 1]; }
#pragma unroll
            for (int nf = 0; nf < 4; nf++) {
                int c = col0 + wn * 32 + nf * 8 + qid * 2;
                float v0 = acc[mf][nf][half * 2 + 0];
                float v1 = acc[mf][nf][half * 2 + 1];
                if (bias) { v0 += bias[c]; v1 += bias[c + 1]; }
                if (xr) {
                    v0 += xa * u1[c]     + xb * u2[c]     + cc[c];
                    v1 += xa * u1[c + 1] + xb * u2[c + 1] + cc[c + 1];
                }
                if (do_relu) { v0 = fmaxf(v0, 0.f); v1 = fmaxf(v1, 0.f); }
                *(float2*)&C[(size_t)r * ldc + c] = make_float2(v0, v1);
            }
        }
    }
}

// ---------------- split-precision 3xTF32 GEMM (fp32-accurate) ----------------
// For accuracy-critical paths: h = x[:,2:]@gat_w (feeds exp) and fc3 (output).
// x = hi + lo with hi=tf32(x), lo=tf32(x-hi); acc += hi*hi + hi*lo + lo*hi.
// BN=64, BM=128, BK=32, 128 threads (2m x 2n warps), warp tile 64x32.
// A loads use float2 (A may be only 8B-aligned, e.g. lda=130 col offset 2).
__global__ void __launch_bounds__(128)
tf32s_gemm(const float* __restrict__ A, int lda,
           const float* __restrict__ W, int ldw,
           const float* __restrict__ bias,
           float* __restrict__ C, int ldc,
           int n, int K) {
    constexpr int BM = 128, BK = 32, BN = 64;
    constexpr int NT = 128;
    constexpr int BSTR = BN + 8;
    __shared__ unsigned Ah[BM][BK + 4];
    __shared__ unsigned Al[BM][BK + 4];
    __shared__ unsigned Bh[BK][BSTR];
    __shared__ unsigned Bl[BK][BSTR];

    const int tid = threadIdx.x;
    const int warp = tid >> 5, lane = tid & 31;
    const int wm = warp >> 1;        // 0..1
    const int wn = warp & 1;         // 0..1
    const int grp = lane >> 2, qid = lane & 3;
    const int row0 = blockIdx.x * BM;
    const int col0 = blockIdx.y * BN;

    float acc[4][4][4] = {};

    for (int kk = 0; kk < K; kk += BK) {
        // A tile via float2 (8B alignment guaranteed)
#pragma unroll
        for (int l = 0; l < (BM * BK / 2) / NT; l++) {
            int i = tid + l * NT;
            int r = i >> 4, c2 = (i & 15) * 2;
            float2 v = (row0 + r < n)
                ? *(const float2*)&A[(size_t)(row0 + r) * lda + kk + c2]
                : make_float2(0.f, 0.f);
            unsigned hx = f2tf(v.x), hy = f2tf(v.y);
            Ah[r][c2]     = hx;
            Ah[r][c2 + 1] = hy;
            Al[r][c2]     = f2tf(v.x - __uint_as_float(hx));
            Al[r][c2 + 1] = f2tf(v.y - __uint_as_float(hy));
        }
        // B tile via float4
#pragma unroll
        for (int l = 0; l < (BK * BN / 4) / NT; l++) {
            int i = tid + l * NT;
            int r = i / (BN / 4), c4 = (i % (BN / 4)) * 4;
            float4 v = *(const float4*)&W[(size_t)(kk + r) * ldw + col0 + c4];
            unsigned h0 = f2tf(v.x), h1 = f2tf(v.y), h2 = f2tf(v.z), h3 = f2tf(v.w);
            Bh[r][c4 + 0] = h0; Bh[r][c4 + 1] = h1;
            Bh[r][c4 + 2] = h2; Bh[r][c4 + 3] = h3;
            Bl[r][c4 + 0] = f2tf(v.x - __uint_as_float(h0));
            Bl[r][c4 + 1] = f2tf(v.y - __uint_as_float(h1));
            Bl[r][c4 + 2] = f2tf(v.z - __uint_as_float(h2));
            Bl[r][c4 + 3] = f2tf(v.w - __uint_as_float(h3));
        }
        __syncthreads();
#pragma unroll
        for (int ks = 0; ks < BK / 8; ks++) {
            const int k0 = ks * 8;
            unsigned ah[4][4], al[4][4], bh[4][2], bl[4][2];
#pragma unroll
            for (int mf = 0; mf < 4; mf++) {
                int r = wm * 64 + mf * 16 + grp;
                ah[mf][0] = Ah[r][k0 + qid];     al[mf][0] = Al[r][k0 + qid];
                ah[mf][1] = Ah[r + 8][k0 + qid]; al[mf][1] = Al[r + 8][k0 + qid];
                ah[mf][2] = Ah[r][k0 + qid + 4]; al[mf][2] = Al[r][k0 + qid + 4];
                ah[mf][3] = Ah[r + 8][k0 + qid + 4]; al[mf][3] = Al[r + 8][k0 + qid + 4];
            }
#pragma unroll
            for (int nf = 0; nf < 4; nf++) {
                int c = wn * 32 + nf * 8 + grp;
                bh[nf][0] = Bh[k0 + qid][c];     bl[nf][0] = Bl[k0 + qid][c];
                bh[nf][1] = Bh[k0 + qid + 4][c]; bl[nf][1] = Bl[k0 + qid + 4][c];
            }
#pragma unroll
            for (int mf = 0; mf < 4; mf++)
#pragma unroll
                for (int nf = 0; nf < 4; nf++) {
                    mma_tf32(acc[mf][nf], al[mf], bh[nf]);
                    mma_tf32(acc[mf][nf], ah[mf], bl[nf]);
                    mma_tf32(acc[mf][nf], ah[mf], bh[nf]);
                }
        }
        __syncthreads();
    }

#pragma unroll
    for (int mf = 0; mf < 4; mf++) {
#pragma unroll
        for (int half = 0; half < 2; half++) {
            int r = row0 + wm * 64 + mf * 16 + grp + half * 8;
            if (r >= n) continue;
#pragma unroll
            for (int nf = 0; nf < 4; nf++) {
                int c = col0 + wn * 32 + nf * 8 + qid * 2;
                float v0 = acc[mf][nf][half * 2 + 0];
                float v1 = acc[mf][nf][half * 2 + 1];
                if (bias) { v0 += bias[c]; v1 += bias[c + 1]; }
                *(float2*)&C[(size_t)r * ldc + c] = make_float2(v0, v1);
            }
        }
    }
}

// -----------------------------------------------------------------------------
extern "C" void kernel_launch(void* const* d_in, const int* in_sizes, int n_in,
                              void* d_out, int out_size) {
    const float* x    = (const float*)d_in[0];
    const void*  ei   = d_in[1];
    const float* w1   = (const float*)d_in[2];
    const float* b1   = (const float*)d_in[3];
    const float* w2   = (const float*)d_in[4];
    const float* b2   = (const float*)d_in[5];
    const float* gatw = (const float*)d_in[6];
    const float* asrc = (const float*)d_in[7];
    const float* adst = (const float*)d_in[8];
    const float* gatb = (const float*)d_in[9];
    const float* fc1w = (const float*)d_in[10];
    const float* fc1b = (const float*)d_in[11];
    const float* fc2w = (const float*)d_in[12];
    const float* fc2b = (const float*)d_in[13];
    const float* fc3w = (const float*)d_in[14];
    const float* fc3b = (const float*)d_in[15];
    float* out = (float*)d_out;

    void *ph, *px3, *ph1, *ph2, *pu1, *pu2, *pcc;
    cudaGetSymbolAddress(&ph,  g_h);
    cudaGetSymbolAddress(&px3, g_x3);
    cudaGetSymbolAddress(&ph1, g_h1);
    cudaGetSymbolAddress(&ph2, g_h2);
    cudaGetSymbolAddress(&pu1, g_u1);
    cudaGetSymbolAddress(&pu2, g_u2);
    cudaGetSymbolAddress(&pcc, g_cc);

    const int GX = (NN + 127) / 128;   // 782

    detect_kernel<<<1, 256>>>((const unsigned*)ei);
    prep_kernel<<<1, 384>>>(w1, b1, w2, b2, gatb, fc1w, fc1b);
    zero_cnt_kernel<<<(NN + 255) / 256, 256>>>();

    // CSR build
    hist_kernel<<<(EE + 255) / 256, 256>>>(ei);
    scan1_kernel<<<NSB, 256>>>();
    scan2_kernel<<<1, 256>>>();
    scan3_kernel<<<NSB, 512>>>();

    // h = x[:,2:130] @ gat_w  (split 3xTF32: fp32-accurate, feeds exp)
    tf32s_gemm<<<dim3(GX, 1), 128>>>(x + 2, 130, gatw, 64, nullptr,
                                     (float*)ph, 64, NN, 128);
    alpha_kernel<<<(NN * 32 + 255) / 256, 256>>>(asrc, adst);
    scatter_kernel<<<(EE + 255) / 256, 256>>>(ei);
    agg_kernel<<<(NN * 32 + 255) / 256, 256>>>();

    // fc1 (TF32): relu( x3 @ fc1_w[128:192,:] + x0*u1 + x1*u2 + cc )
    tf32_gemm<128><<<dim3(GX, 3), 256>>>((const float*)px3, 64, fc1w, 384, 128, nullptr,
                                         (float*)ph1, 384, NN, 64, 1,
                                         x, (const float*)pu1, (const float*)pu2, (const float*)pcc);
    // fc2 (TF32): relu( h1 @ fc2_w + fc2_b )
    tf32_gemm<128><<<dim3(GX, 1), 256>>>((const float*)ph1, 384, fc2w, 128, 0, fc2b,
                                         (float*)ph2, 128, NN, 384, 1,
                                         nullptr, nullptr, nullptr, nullptr);
    // fc3 (split 3xTF32, final output): h2 @ fc3_w + fc3_b
    tf32s_gemm<<<dim3(GX, 1), 128>>>((const float*)ph2, 128, fc3w, 64, fc3b,
                                     out, 64, NN, 128);
}

// round 8
// speedup vs baseline: 2.0940x; 1.0741x over previous
#include <cuda_runtime.h>
#include <math.h>

#define NN 100000
#define EE 1600000
#define NSB ((NN + 511) / 512)   // 196 scan blocks

// ---------------- scratch (device globals; no allocation allowed) ------------
__device__ float g_h  [(size_t)NN * 64];    // GAT h = x[:,2:] @ gat_w
__device__ float g_x3 [(size_t)NN * 64];    // aggregated GAT output (pre-bias)
__device__ float g_h1 [(size_t)NN * 384];   // fc1 activation
__device__ float g_h2 [(size_t)NN * 128];   // fc2 activation
__device__ float g_as [NN];
__device__ float g_ad [NN];
__device__ int   g_cnt[NN];                 // in-degree
__device__ int   g_off[NN];                 // CSR row offsets (exclusive scan)
__device__ int   g_pos[NN];                 // scatter cursors
__device__ int   g_srcs[EE];                // CSR src indices
__device__ float g_exs [EE];                // per-edge exp(leakyrelu(...))
__device__ int   g_bsum[NSB], g_boff[NSB];
__device__ float g_u1[384], g_u2[384], g_cc[384];
__device__ int   g_is64;

// ---------------- int32/int64 edge-index detection ---------------------------
__global__ void detect_kernel(const unsigned* __restrict__ p) {
    __shared__ unsigned sh[256];
    sh[threadIdx.x] = p[2 * threadIdx.x + 1];
    __syncthreads();
    if (threadIdx.x == 0) {
        unsigned o = 0;
        for (int i = 0; i < 256; i++) o |= sh[i];
        g_is64 = (o == 0) ? 1 : 0;
    }
}

// ---------------- precompute rank-2 epilogue vectors for fc1 -----------------
__global__ void prep_kernel(const float* __restrict__ w1, const float* __restrict__ b1,
                            const float* __restrict__ w2, const float* __restrict__ b2,
                            const float* __restrict__ gatb,
                            const float* __restrict__ fc1w, const float* __restrict__ fc1b) {
    int k = threadIdx.x;  // 384 threads
    float s1 = 0.f, s2 = 0.f, c = fc1b[k];
    for (int j = 0; j < 64; j++) {
        float wa = fc1w[(size_t)j * 384 + k];
        float wb = fc1w[(size_t)(64 + j) * 384 + k];
        float wc = fc1w[(size_t)(128 + j) * 384 + k];
        s1 += w1[j] * wa;
        s2 += w2[j] * wb;
        c  += b1[j] * wa + b2[j] * wb + gatb[j] * wc;
    }
    g_u1[k] = s1; g_u2[k] = s2; g_cc[k] = c;
}

__global__ void zero_cnt_kernel() {
    int i = blockIdx.x * blockDim.x + threadIdx.x;
    if (i < NN) g_cnt[i] = 0;
}

// ---------------- degree histogram -------------------------------------------
__global__ void hist_kernel(const void* __restrict__ idx) {
    int e = blockIdx.x * blockDim.x + threadIdx.x;
    if (e >= EE) return;
    int d = g_is64 ? (int)((const long long*)idx)[EE + e]
                   : ((const int*)idx)[EE + e];
    atomicAdd(&g_cnt[d], 1);
}

// ---------------- 3-kernel exclusive scan over g_cnt -------------------------
__global__ void scan1_kernel() {               // grid NSB, 256 thr
    __shared__ int sh[256];
    int b = blockIdx.x, t = threadIdx.x;
    int i0 = b * 512 + t;
    int v = 0;
    if (i0 < NN) v += g_cnt[i0];
    if (i0 + 256 < NN) v += g_cnt[i0 + 256];
    sh[t] = v; __syncthreads();
    for (int o = 128; o; o >>= 1) { if (t < o) sh[t] += sh[t + o]; __syncthreads(); }
    if (t == 0) g_bsum[b] = sh[0];
}

__global__ void scan2_kernel() {               // 1 block, 256 thr (NSB <= 256)
    __shared__ int sh[256];
    int t = threadIdx.x;
    int v = (t < NSB) ? g_bsum[t] : 0;
    sh[t] = v;
    for (int o = 1; o < 256; o <<= 1) {
        __syncthreads();
        int u = (t >= o) ? sh[t - o] : 0;
        __syncthreads();
        sh[t] += u;
    }
    __syncthreads();
    if (t < NSB) g_boff[t] = sh[t] - v;        // exclusive
}

__global__ void scan3_kernel() {               // grid NSB, 512 thr
    __shared__ int sh[512];
    int b = blockIdx.x, t = threadIdx.x;
    int i = b * 512 + t;
    int c = (i < NN) ? g_cnt[i] : 0;
    sh[t] = c;
    for (int o = 1; o < 512; o <<= 1) {
        __syncthreads();
        int u = (t >= o) ? sh[t - o] : 0;
        __syncthreads();
        sh[t] += u;
    }
    __syncthreads();
    if (i < NN) {
        int excl = sh[t] - c + g_boff[b];
        g_off[i] = excl;
        g_pos[i] = excl;
    }
}

// ---------------- alpha_src / alpha_dst per node (warp per node) -------------
__global__ void alpha_kernel(const float* __restrict__ asrc, const float* __restrict__ adst) {
    int gw = (int)((blockIdx.x * blockDim.x + threadIdx.x) >> 5);
    int lane = threadIdx.x & 31;
    if (gw >= NN) return;
    float h0 = g_h[(size_t)gw * 64 + lane];
    float h1 = g_h[(size_t)gw * 64 + 32 + lane];
    float s = h0 * asrc[lane] + h1 * asrc[32 + lane];
    float d = h0 * adst[lane] + h1 * adst[32 + lane];
#pragma unroll
    for (int o = 16; o; o >>= 1) {
        s += __shfl_xor_sync(0xffffffffu, s, o);
        d += __shfl_xor_sync(0xffffffffu, d, o);
    }
    if (lane == 0) { g_as[gw] = s; g_ad[gw] = d; }
}

// ---------------- scatter into CSR + per-edge exp ----------------------------
__global__ void scatter_kernel(const void* __restrict__ idx) {
    int e = blockIdx.x * blockDim.x + threadIdx.x;
    if (e >= EE) return;
    int s, d;
    if (g_is64) {
        const long long* q = (const long long*)idx;
        s = (int)q[e]; d = (int)q[EE + e];
    } else {
        const int* q = (const int*)idx;
        s = q[e]; d = q[EE + e];
    }
    float v = g_as[s] + g_ad[d];
    v = (v > 0.f) ? v : 0.2f * v;
    float ex = expf(v);
    int p = atomicAdd(&g_pos[d], 1);
    g_srcs[p] = s;
    g_exs[p] = ex;
}

// ---------------- CSR aggregation: warp per destination node -----------------
__global__ void agg_kernel() {
    int node = (int)((blockIdx.x * (size_t)blockDim.x + threadIdx.x) >> 5);
    int lane = threadIdx.x & 31;
    if (node >= NN) return;
    int beg = g_off[node];
    int cnt = g_cnt[node];
    float v = g_as[node] + g_ad[node];
    v = (v > 0.f) ? v : 0.2f * v;
    float ex_self = expf(v);
    float dsum = 0.f;
    for (int i = lane; i < cnt; i += 32) dsum += g_exs[beg + i];
#pragma unroll
    for (int o = 16; o; o >>= 1) dsum += __shfl_xor_sync(0xffffffffu, dsum, o);
    float invd = 1.f / (dsum + ex_self + 1e-16f);
    float2 acc;
    {
        float2 hv = *(const float2*)(g_h + (size_t)node * 64 + lane * 2);
        float c = ex_self * invd;
        acc.x = c * hv.x; acc.y = c * hv.y;
    }
#pragma unroll 4
    for (int e = 0; e < cnt; e++) {
        int s = g_srcs[beg + e];
        float c = g_exs[beg + e] * invd;
        float2 hv = *(const float2*)(g_h + (size_t)s * 64 + lane * 2);
        acc.x += c * hv.x; acc.y += c * hv.y;
    }
    *(float2*)(g_x3 + (size_t)node * 64 + lane * 2) = acc;
}

// ---------------- TF32 / cp.async helpers -------------------------------------
__device__ __forceinline__ unsigned f2tf(float x) {
    unsigned r; asm("cvt.rna.tf32.f32 %0, %1;" : "=r"(r) : "f"(x)); return r;
}
__device__ __forceinline__ void mma_tf32(float* d, const unsigned* a, const unsigned* b) {
    asm volatile(
        "mma.sync.aligned.m16n8k8.row.col.f32.tf32.tf32.f32 "
        "{%0,%1,%2,%3}, {%4,%5,%6,%7}, {%8,%9}, {%0,%1,%2,%3};\n"
        : "+f"(d[0]), "+f"(d[1]), "+f"(d[2]), "+f"(d[3])
        : "r"(a[0]), "r"(a[1]), "r"(a[2]), "r"(a[3]), "r"(b[0]), "r"(b[1]));
}
__device__ __forceinline__ void cp16(float* smem, const float* g, bool valid) {
    unsigned sa = (unsigned)__cvta_generic_to_shared(smem);
    int sz = valid ? 16 : 0;
    asm volatile("cp.async.cg.shared.global [%0], [%1], 16, %2;" :: "r"(sa), "l"(g), "r"(sz));
}
__device__ __forceinline__ void cp8(float* smem, const float* g, bool valid) {
    unsigned sa = (unsigned)__cvta_generic_to_shared(smem);
    int sz = valid ? 8 : 0;
    asm volatile("cp.async.ca.shared.global [%0], [%1], 8, %2;" :: "r"(sa), "l"(g), "r"(sz));
}
#define CP_COMMIT() asm volatile("cp.async.commit_group;")
#define CP_WAIT1()  asm volatile("cp.async.wait_group 1;")
#define CP_WAIT0()  asm volatile("cp.async.wait_group 0;")

// ---------------- plain TF32 GEMM, 2-stage cp.async pipeline (fc1 / fc2) ------
// BM=128, BN=128, BK=32, 256 threads (2m x 4n warps), warp tile 64x32.
// Raw floats staged in dynamic smem; tf32 cvt in fragment path.
#define TG_ASZ (128 * 36)
#define TG_BSZ (32 * 136)
#define TG_SMEM ((2 * (TG_ASZ + TG_BSZ)) * 4)
__global__ void __launch_bounds__(256)
tf32_gemm(const float* __restrict__ A, int lda,
          const float* __restrict__ W, int ldw, int wrow0,
          const float* __restrict__ bias,
          float* __restrict__ C, int ldc,
          int n, int K, int do_relu,
          const float* __restrict__ xr,
          const float* __restrict__ u1,
          const float* __restrict__ u2,
          const float* __restrict__ cc) {
    constexpr int BM = 128, BK = 32, BN = 128;
    extern __shared__ float smem[];
    float* Asf = smem;               // [2][128][36]
    float* Bsf = smem + 2 * TG_ASZ;  // [2][32][136]

    const int tid = threadIdx.x;
    const int warp = tid >> 5, lane = tid & 31;
    const int wm = warp >> 2;        // 0..1
    const int wn = warp & 3;         // 0..3
    const int grp = lane >> 2, qid = lane & 3;
    const int row0 = blockIdx.x * BM;
    const int col0 = blockIdx.y * BN;
    const int nk = K / BK;

    float acc[4][4][4] = {};

    // tile loader: stage s, k-chunk kk
    auto load_tile = [&](int s, int kk) {
        float* At = Asf + s * TG_ASZ;
        float* Bt = Bsf + s * TG_BSZ;
#pragma unroll
        for (int l = 0; l < 4; l++) {               // A: 1024 16B chunks / 256 thr
            int i = tid + l * 256;
            int r = i >> 3, c4 = (i & 7) * 4;
            int gr = row0 + r;
            bool v = gr < n;
            const float* src = A + (size_t)(v ? gr : n - 1) * lda + kk + c4;
            cp16(&At[r * 36 + c4], src, v);
        }
#pragma unroll
        for (int l = 0; l < 4; l++) {               // B: 1024 16B chunks / 256 thr
            int i = tid + l * 256;
            int r = i >> 5, c4 = (i & 31) * 4;
            cp16(&Bt[r * 136 + c4], &W[(size_t)(wrow0 + kk + r) * ldw + col0 + c4], true);
        }
        CP_COMMIT();
    };

    load_tile(0, 0);
    for (int t = 0; t < nk; t++) {
        if (t + 1 < nk) load_tile((t + 1) & 1, (t + 1) * BK);
        if (t + 1 < nk) CP_WAIT1(); else CP_WAIT0();
        __syncthreads();
        const float* At = Asf + (t & 1) * TG_ASZ;
        const float* Bt = Bsf + (t & 1) * TG_BSZ;
#pragma unroll
        for (int ks = 0; ks < BK / 8; ks++) {
            const int k0 = ks * 8;
            unsigned a[4][4], b[4][2];
#pragma unroll
            for (int mf = 0; mf < 4; mf++) {
                int r = wm * 64 + mf * 16 + grp;
                a[mf][0] = f2tf(At[r * 36 + k0 + qid]);
                a[mf][1] = f2tf(At[(r + 8) * 36 + k0 + qid]);
                a[mf][2] = f2tf(At[r * 36 + k0 + qid + 4]);
                a[mf][3] = f2tf(At[(r + 8) * 36 + k0 + qid + 4]);
            }
#pragma unroll
            for (int nf = 0; nf < 4; nf++) {
                int c = wn * 32 + nf * 8 + grp;
                b[nf][0] = f2tf(Bt[(k0 + qid) * 136 + c]);
                b[nf][1] = f2tf(Bt[(k0 + qid + 4) * 136 + c]);
            }
#pragma unroll
            for (int mf = 0; mf < 4; mf++)
#pragma unroll
                for (int nf = 0; nf < 4; nf++)
                    mma_tf32(acc[mf][nf], a[mf], b[nf]);
        }
        __syncthreads();
    }

#pragma unroll
    for (int mf = 0; mf < 4; mf++) {
#pragma unroll
        for (int half = 0; half < 2; half++) {
            int r = row0 + wm * 64 + mf * 16 + grp + half * 8;
            if (r >= n) continue;
            float xa = 0.f, xb = 0.f;
            if (xr) { xa = xr[(size_t)r * 130]; xb = xr[(size_t)r * 130 + 1]; }
#pragma unroll
            for (int nf = 0; nf < 4; nf++) {
                int c = col0 + wn * 32 + nf * 8 + qid * 2;
                float v0 = acc[mf][nf][half * 2 + 0];
                float v1 = acc[mf][nf][half * 2 + 1];
                if (bias) { v0 += bias[c]; v1 += bias[c + 1]; }
                if (xr) {
                    v0 += xa * u1[c]     + xb * u2[c]     + cc[c];
                    v1 += xa * u1[c + 1] + xb * u2[c + 1] + cc[c + 1];
                }
                if (do_relu) { v0 = fmaxf(v0, 0.f); v1 = fmaxf(v1, 0.f); }
                *(float2*)&C[(size_t)r * ldc + c] = make_float2(v0, v1);
            }
        }
    }
}

// ---------------- split 3xTF32 GEMM, 2-stage cp.async (h / fc3) ---------------
// fp32-accurate: x = hi + lo; acc += hi*hi + hi*lo + lo*hi. Split happens in
// the fragment path, so smem stages raw floats only.
// BM=128, BN=64, BK=32, 128 threads (2m x 2n warps).
// A loads via 8B cp.async (A may be only 8B-aligned: lda=130, col offset 2).
#define TS_ASZ (128 * 36)
#define TS_BSZ (32 * 72)
#define TS_SMEM ((2 * (TS_ASZ + TS_BSZ)) * 4)
__global__ void __launch_bounds__(128)
tf32s_gemm(const float* __restrict__ A, int lda,
           const float* __restrict__ W, int ldw,
           const float* __restrict__ bias,
           float* __restrict__ C, int ldc,
           int n, int K) {
    constexpr int BM = 128, BK = 32, BN = 64;
    extern __shared__ float smem[];
    float* Asf = smem;               // [2][128][36]
    float* Bsf = smem + 2 * TS_ASZ;  // [2][32][72]

    const int tid = threadIdx.x;
    const int warp = tid >> 5, lane = tid & 31;
    const int wm = warp >> 1;        // 0..1
    const int wn = warp & 1;         // 0..1
    const int grp = lane >> 2, qid = lane & 3;
    const int row0 = blockIdx.x * BM;
    const int col0 = blockIdx.y * BN;
    const int nk = K / BK;

    float acc[4][4][4] = {};

    auto load_tile = [&](int s, int kk) {
        float* At = Asf + s * TS_ASZ;
        float* Bt = Bsf + s * TS_BSZ;
#pragma unroll
        for (int l = 0; l < 16; l++) {              // A: 2048 8B chunks / 128 thr
            int i = tid + l * 128;
            int r = i >> 4, c2 = (i & 15) * 2;
            int gr = row0 + r;
            bool v = gr < n;
            const float* src = A + (size_t)(v ? gr : n - 1) * lda + kk + c2;
            cp8(&At[r * 36 + c2], src, v);
        }
#pragma unroll
        for (int l = 0; l < 4; l++) {               // B: 512 16B chunks / 128 thr
            int i = tid + l * 128;
            int r = i >> 4, c4 = (i & 15) * 4;
            cp16(&Bt[r * 72 + c4], &W[(size_t)(kk + r) * ldw + col0 + c4], true);
        }
        CP_COMMIT();
    };

    load_tile(0, 0);
    for (int t = 0; t < nk; t++) {
        if (t + 1 < nk) load_tile((t + 1) & 1, (t + 1) * BK);
        if (t + 1 < nk) CP_WAIT1(); else CP_WAIT0();
        __syncthreads();
        const float* At = Asf + (t & 1) * TS_ASZ;
        const float* Bt = Bsf + (t & 1) * TS_BSZ;
#pragma unroll
        for (int ks = 0; ks < BK / 8; ks++) {
            const int k0 = ks * 8;
            unsigned ah[4][4], al[4][4], bh[4][2], bl[4][2];
#pragma unroll
            for (int mf = 0; mf < 4; mf++) {
                int r = wm * 64 + mf * 16 + grp;
                float x0 = At[r * 36 + k0 + qid];
                float x1 = At[(r + 8) * 36 + k0 + qid];
                float x2 = At[r * 36 + k0 + qid + 4];
                float x3 = At[(r + 8) * 36 + k0 + qid + 4];
                ah[mf][0] = f2tf(x0); al[mf][0] = f2tf(x0 - __uint_as_float(ah[mf][0]));
                ah[mf][1] = f2tf(x1); al[mf][1] = f2tf(x1 - __uint_as_float(ah[mf][1]));
                ah[mf][2] = f2tf(x2); al[mf][2] = f2tf(x2 - __uint_as_float(ah[mf][2]));
                ah[mf][3] = f2tf(x3); al[mf][3] = f2tf(x3 - __uint_as_float(ah[mf][3]));
            }
#pragma unroll
            for (int nf = 0; nf < 4; nf++) {
                int c = wn * 32 + nf * 8 + grp;
                float y0 = Bt[(k0 + qid) * 72 + c];
                float y1 = Bt[(k0 + qid + 4) * 72 + c];
                bh[nf][0] = f2tf(y0); bl[nf][0] = f2tf(y0 - __uint_as_float(bh[nf][0]));
                bh[nf][1] = f2tf(y1); bl[nf][1] = f2tf(y1 - __uint_as_float(bh[nf][1]));
            }
#pragma unroll
            for (int mf = 0; mf < 4; mf++)
#pragma unroll
                for (int nf = 0; nf < 4; nf++) {
                    mma_tf32(acc[mf][nf], al[mf], bh[nf]);
                    mma_tf32(acc[mf][nf], ah[mf], bl[nf]);
                    mma_tf32(acc[mf][nf], ah[mf], bh[nf]);
                }
        }
        __syncthreads();
    }

#pragma unroll
    for (int mf = 0; mf < 4; mf++) {
#pragma unroll
        for (int half = 0; half < 2; half++) {
            int r = row0 + wm * 64 + mf * 16 + grp + half * 8;
            if (r >= n) continue;
#pragma unroll
            for (int nf = 0; nf < 4; nf++) {
                int c = col0 + wn * 32 + nf * 8 + qid * 2;
                float v0 = acc[mf][nf][half * 2 + 0];
                float v1 = acc[mf][nf][half * 2 + 1];
                if (bias) { v0 += bias[c]; v1 += bias[c + 1]; }
                *(float2*)&C[(size_t)r * ldc + c] = make_float2(v0, v1);
            }
        }
    }
}

// -----------------------------------------------------------------------------
extern "C" void kernel_launch(void* const* d_in, const int* in_sizes, int n_in,
                              void* d_out, int out_size) {
    const float* x    = (const float*)d_in[0];
    const void*  ei   = d_in[1];
    const float* w1   = (const float*)d_in[2];
    const float* b1   = (const float*)d_in[3];
    const float* w2   = (const float*)d_in[4];
    const float* b2   = (const float*)d_in[5];
    const float* gatw = (const float*)d_in[6];
    const float* asrc = (const float*)d_in[7];
    const float* adst = (const float*)d_in[8];
    const float* gatb = (const float*)d_in[9];
    const float* fc1w = (const float*)d_in[10];
    const float* fc1b = (const float*)d_in[11];
    const float* fc2w = (const float*)d_in[12];
    const float* fc2b = (const float*)d_in[13];
    const float* fc3w = (const float*)d_in[14];
    const float* fc3b = (const float*)d_in[15];
    float* out = (float*)d_out;

    void *ph, *px3, *ph1, *ph2, *pu1, *pu2, *pcc;
    cudaGetSymbolAddress(&ph,  g_h);
    cudaGetSymbolAddress(&px3, g_x3);
    cudaGetSymbolAddress(&ph1, g_h1);
    cudaGetSymbolAddress(&ph2, g_h2);
    cudaGetSymbolAddress(&pu1, g_u1);
    cudaGetSymbolAddress(&pu2, g_u2);
    cudaGetSymbolAddress(&pcc, g_cc);

    static int attr_done = 0;
    if (!attr_done) {
        cudaFuncSetAttribute(tf32_gemm,  cudaFuncAttributeMaxDynamicSharedMemorySize, TG_SMEM);
        cudaFuncSetAttribute(tf32s_gemm, cudaFuncAttributeMaxDynamicSharedMemorySize, TS_SMEM);
        attr_done = 1;
    }

    const int GX = (NN + 127) / 128;   // 782

    detect_kernel<<<1, 256>>>((const unsigned*)ei);
    prep_kernel<<<1, 384>>>(w1, b1, w2, b2, gatb, fc1w, fc1b);
    zero_cnt_kernel<<<(NN + 255) / 256, 256>>>();

    // CSR build
    hist_kernel<<<(EE + 255) / 256, 256>>>(ei);
    scan1_kernel<<<NSB, 256>>>();
    scan2_kernel<<<1, 256>>>();
    scan3_kernel<<<NSB, 512>>>();

    // h = x[:,2:130] @ gat_w  (split 3xTF32: fp32-accurate, feeds exp)
    tf32s_gemm<<<dim3(GX, 1), 128, TS_SMEM>>>(x + 2, 130, gatw, 64, nullptr,
                                              (float*)ph, 64, NN, 128);
    alpha_kernel<<<(NN * 32 + 255) / 256, 256>>>(asrc, adst);
    scatter_kernel<<<(EE + 255) / 256, 256>>>(ei);
    agg_kernel<<<(NN * 32 + 255) / 256, 256>>>();

    // fc1 (TF32): relu( x3 @ fc1_w[128:192,:] + x0*u1 + x1*u2 + cc )
    tf32_gemm<<<dim3(GX, 3), 256, TG_SMEM>>>((const float*)px3, 64, fc1w, 384, 128, nullptr,
                                             (float*)ph1, 384, NN, 64, 1,
                                             x, (const float*)pu1, (const float*)pu2, (const float*)pcc);
    // fc2 (TF32): relu( h1 @ fc2_w + fc2_b )
    tf32_gemm<<<dim3(GX, 1), 256, TG_SMEM>>>((const float*)ph1, 384, fc2w, 128, 0, fc2b,
                                             (float*)ph2, 128, NN, 384, 1,
                                             nullptr, nullptr, nullptr, nullptr);
    // fc3 (split 3xTF32, final output): h2 @ fc3_w + fc3_b
    tf32s_gemm<<<dim3(GX, 1), 128, TS_SMEM>>>((const float*)ph2, 128, fc3w, 64, fc3b,
                                              out, 64, NN, 128);
}

// round 9
// speedup vs baseline: 2.5016x; 1.1947x over previous
#include <cuda_runtime.h>
#include <cuda_fp16.h>
#include <math.h>

#define NN 100000
#define EE 1600000
#define NSB ((NN + 511) / 512)   // 196 scan blocks

// ---------------- scratch (device globals; no allocation allowed) ------------
__device__ float  g_h  [(size_t)NN * 64];    // GAT h = x[:,2:] @ gat_w (fp32)
__device__ __half g_x3h[(size_t)NN * 64];    // aggregated GAT output (fp16)
__device__ __half g_h1h[(size_t)NN * 384];   // fc1 activation (fp16)
__device__ float  g_h2 [(size_t)NN * 128];   // fc2 activation (fp32)
__device__ float  g_as [NN];
__device__ float  g_ad [NN];
__device__ int    g_cnt[NN];                 // in-degree
__device__ int    g_off[NN];                 // CSR row offsets (exclusive scan)
__device__ int    g_pos[NN];                 // scatter cursors
__device__ float2 g_edge[EE];                // CSR (src bit-cast, exp) pairs
__device__ int    g_bsum[NSB], g_boff[NSB];
__device__ float  g_u1[384], g_u2[384], g_cc[384];
__device__ __half g_w1t[384 * 64];           // fc1_w[128:192,:]^T fp16  [n][k]
__device__ __half g_w2t[128 * 384];          // fc2_w^T fp16             [n][k]
__device__ int    g_is64;

// ---------------- int32/int64 edge-index detection ---------------------------
__global__ void detect_kernel(const unsigned* __restrict__ p) {
    __shared__ unsigned sh[256];
    sh[threadIdx.x] = p[2 * threadIdx.x + 1];
    __syncthreads();
    if (threadIdx.x == 0) {
        unsigned o = 0;
        for (int i = 0; i < 256; i++) o |= sh[i];
        g_is64 = (o == 0) ? 1 : 0;
    }
}

// ---------------- precompute rank-2 epilogue vectors for fc1 -----------------
__global__ void prep_kernel(const float* __restrict__ w1, const float* __restrict__ b1,
                            const float* __restrict__ w2, const float* __restrict__ b2,
                            const float* __restrict__ gatb,
                            const float* __restrict__ fc1w, const float* __restrict__ fc1b) {
    int k = threadIdx.x;  // 384 threads
    float s1 = 0.f, s2 = 0.f, c = fc1b[k];
    for (int j = 0; j < 64; j++) {
        float wa = fc1w[(size_t)j * 384 + k];
        float wb = fc1w[(size_t)(64 + j) * 384 + k];
        float wc = fc1w[(size_t)(128 + j) * 384 + k];
        s1 += w1[j] * wa;
        s2 += w2[j] * wb;
        c  += b1[j] * wa + b2[j] * wb + gatb[j] * wc;
    }
    g_u1[k] = s1; g_u2[k] = s2; g_cc[k] = c;
}

// ---------------- weight transpose + fp16 cast --------------------------------
__global__ void tr_kernel(const float* __restrict__ fc1w, const float* __restrict__ fc2w) {
    int i = blockIdx.x * 256 + threadIdx.x;
    if (i < 384 * 64) {                       // g_w1t[c][k] = fc1w[128+k][c]
        int c = i >> 6, k = i & 63;
        g_w1t[i] = __float2half_rn(fc1w[(size_t)(128 + k) * 384 + c]);
    }
    if (i < 128 * 384) {                      // g_w2t[c][k] = fc2w[k][c]
        int c = i / 384, k = i % 384;
        g_w2t[i] = __float2half_rn(fc2w[(size_t)k * 128 + c]);
    }
}

__global__ void zero_cnt_kernel() {
    int i = blockIdx.x * blockDim.x + threadIdx.x;
    if (i < NN) g_cnt[i] = 0;
}

// ---------------- degree histogram -------------------------------------------
__global__ void hist_kernel(const void* __restrict__ idx) {
    int e = blockIdx.x * blockDim.x + threadIdx.x;
    if (e >= EE) return;
    int d = g_is64 ? (int)((const long long*)idx)[EE + e]
                   : ((const int*)idx)[EE + e];
    atomicAdd(&g_cnt[d], 1);
}

// ---------------- 3-kernel exclusive scan over g_cnt -------------------------
__global__ void scan1_kernel() {
    __shared__ int sh[256];
    int b = blockIdx.x, t = threadIdx.x;
    int i0 = b * 512 + t;
    int v = 0;
    if (i0 < NN) v += g_cnt[i0];
    if (i0 + 256 < NN) v += g_cnt[i0 + 256];
    sh[t] = v; __syncthreads();
    for (int o = 128; o; o >>= 1) { if (t < o) sh[t] += sh[t + o]; __syncthreads(); }
    if (t == 0) g_bsum[b] = sh[0];
}

__global__ void scan2_kernel() {
    __shared__ int sh[256];
    int t = threadIdx.x;
    int v = (t < NSB) ? g_bsum[t] : 0;
    sh[t] = v;
    for (int o = 1; o < 256; o <<= 1) {
        __syncthreads();
        int u = (t >= o) ? sh[t - o] : 0;
        __syncthreads();
        sh[t] += u;
    }
    __syncthreads();
    if (t < NSB) g_boff[t] = sh[t] - v;
}

__global__ void scan3_kernel() {
    __shared__ int sh[512];
    int b = blockIdx.x, t = threadIdx.x;
    int i = b * 512 + t;
    int c = (i < NN) ? g_cnt[i] : 0;
    sh[t] = c;
    for (int o = 1; o < 512; o <<= 1) {
        __syncthreads();
        int u = (t >= o) ? sh[t - o] : 0;
        __syncthreads();
        sh[t] += u;
    }
    __syncthreads();
    if (i < NN) {
        int excl = sh[t] - c + g_boff[b];
        g_off[i] = excl;
        g_pos[i] = excl;
    }
}

// ---------------- alpha_src / alpha_dst per node (warp per node) -------------
__global__ void alpha_kernel(const float* __restrict__ asrc, const float* __restrict__ adst) {
    int gw = (int)((blockIdx.x * blockDim.x + threadIdx.x) >> 5);
    int lane = threadIdx.x & 31;
    if (gw >= NN) return;
    float h0 = g_h[(size_t)gw * 64 + lane];
    float h1 = g_h[(size_t)gw * 64 + 32 + lane];
    float s = h0 * asrc[lane] + h1 * asrc[32 + lane];
    float d = h0 * adst[lane] + h1 * adst[32 + lane];
#pragma unroll
    for (int o = 16; o; o >>= 1) {
        s += __shfl_xor_sync(0xffffffffu, s, o);
        d += __shfl_xor_sync(0xffffffffu, d, o);
    }
    if (lane == 0) { g_as[gw] = s; g_ad[gw] = d; }
}

// ---------------- scatter into CSR: packed (src, exp) ------------------------
__global__ void scatter_kernel(const void* __restrict__ idx) {
    int e = blockIdx.x * blockDim.x + threadIdx.x;
    if (e >= EE) return;
    int s, d;
    if (g_is64) {
        const long long* q = (const long long*)idx;
        s = (int)q[e]; d = (int)q[EE + e];
    } else {
        const int* q = (const int*)idx;
        s = q[e]; d = q[EE + e];
    }
    float v = g_as[s] + g_ad[d];
    v = (v > 0.f) ? v : 0.2f * v;
    float ex = expf(v);
    int p = atomicAdd(&g_pos[d], 1);
    g_edge[p] = make_float2(__int_as_float(s), ex);
}

// ---------------- CSR aggregation: warp per destination node -----------------
__global__ void agg_kernel() {
    int node = (int)((blockIdx.x * (size_t)blockDim.x + threadIdx.x) >> 5);
    int lane = threadIdx.x & 31;
    if (node >= NN) return;
    int beg = g_off[node];
    int cnt = g_cnt[node];
    float v = g_as[node] + g_ad[node];
    v = (v > 0.f) ? v : 0.2f * v;
    float ex_self = expf(v);
    float dsum = 0.f;
    for (int i = lane; i < cnt; i += 32) dsum += g_edge[beg + i].y;
#pragma unroll
    for (int o = 16; o; o >>= 1) dsum += __shfl_xor_sync(0xffffffffu, dsum, o);
    float invd = 1.f / (dsum + ex_self + 1e-16f);
    float2 acc;
    {
        float2 hv = *(const float2*)(g_h + (size_t)node * 64 + lane * 2);
        float c = ex_self * invd;
        acc.x = c * hv.x; acc.y = c * hv.y;
    }
#pragma unroll 4
    for (int e = 0; e < cnt; e++) {
        float2 ev = g_edge[beg + e];
        int s = __float_as_int(ev.x);
        float c = ev.y * invd;
        float2 hv = *(const float2*)(g_h + (size_t)s * 64 + lane * 2);
        acc.x += c * hv.x; acc.y += c * hv.y;
    }
    *(half2*)(g_x3h + (size_t)node * 64 + lane * 2) = __floats2half2_rn(acc.x, acc.y);
}

// ---------------- TF32 / cp.async helpers -------------------------------------
__device__ __forceinline__ unsigned f2tf(float x) {
    unsigned r; asm("cvt.rna.tf32.f32 %0, %1;" : "=r"(r) : "f"(x)); return r;
}
__device__ __forceinline__ void mma_tf32(float* d, const unsigned* a, const unsigned* b) {
    asm volatile(
        "mma.sync.aligned.m16n8k8.row.col.f32.tf32.tf32.f32 "
        "{%0,%1,%2,%3}, {%4,%5,%6,%7}, {%8,%9}, {%0,%1,%2,%3};\n"
        : "+f"(d[0]), "+f"(d[1]), "+f"(d[2]), "+f"(d[3])
        : "r"(a[0]), "r"(a[1]), "r"(a[2]), "r"(a[3]), "r"(b[0]), "r"(b[1]));
}
__device__ __forceinline__ void mma_f16(float* d, const unsigned* a, const unsigned* b) {
    asm volatile(
        "mma.sync.aligned.m16n8k16.row.col.f32.f16.f16.f32 "
        "{%0,%1,%2,%3}, {%4,%5,%6,%7}, {%8,%9}, {%0,%1,%2,%3};\n"
        : "+f"(d[0]), "+f"(d[1]), "+f"(d[2]), "+f"(d[3])
        : "r"(a[0]), "r"(a[1]), "r"(a[2]), "r"(a[3]), "r"(b[0]), "r"(b[1]));
}
__device__ __forceinline__ void cp16(void* smem, const void* g, bool valid) {
    unsigned sa = (unsigned)__cvta_generic_to_shared(smem);
    int sz = valid ? 16 : 0;
    asm volatile("cp.async.cg.shared.global [%0], [%1], 16, %2;" :: "r"(sa), "l"(g), "r"(sz));
}
__device__ __forceinline__ void cp8(void* smem, const void* g, bool valid) {
    unsigned sa = (unsigned)__cvta_generic_to_shared(smem);
    int sz = valid ? 8 : 0;
    asm volatile("cp.async.ca.shared.global [%0], [%1], 8, %2;" :: "r"(sa), "l"(g), "r"(sz));
}
#define CP_COMMIT() asm volatile("cp.async.commit_group;")
#define CP_WAIT1()  asm volatile("cp.async.wait_group 1;")
#define CP_WAIT0()  asm volatile("cp.async.wait_group 0;")

// ---------------- fp16 GEMM, 2-stage cp.async pipeline (fc1 / fc2) ------------
// BM=128, BN=128, BK=64, 256 threads (2m x 4n warps), warp tile 64x32,
// m16n8k16 fragments. A fp16 row-major; Wt fp16 [n][k] (pre-transposed).
// OUT_HALF: 1 -> C is __half (h1), 0 -> C is float (h2).
#define HG_STR  72
#define HG_TSZ  (128 * HG_STR)                 // halves per (A or B) tile
#define HG_SMEM (4 * HG_TSZ * 2)               // 2 stages * (A+B) * 2B = 73728
template<int OUT_HALF>
__global__ void __launch_bounds__(256)
f16_gemm(const __half* __restrict__ A, int lda,
         const __half* __restrict__ Wt, int ldwt,
         const float* __restrict__ bias,
         void* __restrict__ Cv, int ldc,
         int n, int K, int do_relu,
         const float* __restrict__ xr,
         const float* __restrict__ u1,
         const float* __restrict__ u2,
         const float* __restrict__ cc) {
    constexpr int BM = 128, BK = 64;
    extern __shared__ __half smh[];
    __half* Asf = smh;                 // [2][128][72]
    __half* Bsf = smh + 2 * HG_TSZ;    // [2][128][72]

    const int tid = threadIdx.x;
    const int warp = tid >> 5, lane = tid & 31;
    const int wm = warp >> 2;          // 0..1
    const int wn = warp & 3;           // 0..3
    const int grp = lane >> 2, qid = lane & 3;
    const int row0 = blockIdx.x * BM;
    const int col0 = blockIdx.y * 128;
    const int nk = K / BK;

    float acc[4][4][4] = {};

    auto load_tile = [&](int s, int kk) {
        __half* At = Asf + s * HG_TSZ;
        __half* Bt = Bsf + s * HG_TSZ;
#pragma unroll
        for (int l = 0; l < 4; l++) {              // A: 1024 16B chunks
            int i = tid + l * 256;
            int r = i >> 3, c8 = (i & 7) * 8;
            int gr = row0 + r;
            bool v = gr < n;
            cp16(&At[r * HG_STR + c8], A + (size_t)(v ? gr : 0) * lda + kk + c8, v);
        }
#pragma unroll
        for (int l = 0; l < 4; l++) {              // B: 1024 16B chunks
            int i = tid + l * 256;
            int r = i >> 3, c8 = (i & 7) * 8;
            cp16(&Bt[r * HG_STR + c8], Wt + (size_t)(col0 + r) * ldwt + kk + c8, true);
        }
        CP_COMMIT();
    };

    load_tile(0, 0);
    for (int t = 0; t < nk; t++) {
        if (t + 1 < nk) load_tile((t + 1) & 1, (t + 1) * BK);
        if (t + 1 < nk) CP_WAIT1(); else CP_WAIT0();
        __syncthreads();
        const __half* At = Asf + (t & 1) * HG_TSZ;
        const __half* Bt = Bsf + (t & 1) * HG_TSZ;
#pragma unroll
        for (int ks = 0; ks < BK / 16; ks++) {
            const int k0 = ks * 16;
            unsigned a[4][4], b[4][2];
#pragma unroll
            for (int mf = 0; mf < 4; mf++) {
                int r = wm * 64 + mf * 16 + grp;
                a[mf][0] = *(const unsigned*)&At[r * HG_STR + k0 + 2 * qid];
                a[mf][1] = *(const unsigned*)&At[(r + 8) * HG_STR + k0 + 2 * qid];
                a[mf][2] = *(const unsigned*)&At[r * HG_STR + k0 + 2 * qid + 8];
                a[mf][3] = *(const unsigned*)&At[(r + 8) * HG_STR + k0 + 2 * qid + 8];
            }
#pragma unroll
            for (int nf = 0; nf < 4; nf++) {
                int c = wn * 32 + nf * 8 + grp;
                b[nf][0] = *(const unsigned*)&Bt[c * HG_STR + k0 + 2 * qid];
                b[nf][1] = *(const unsigned*)&Bt[c * HG_STR + k0 + 2 * qid + 8];
            }
#pragma unroll
            for (int mf = 0; mf < 4; mf++)
#pragma unroll
                for (int nf = 0; nf < 4; nf++)
                    mma_f16(acc[mf][nf], a[mf], b[nf]);
        }
        __syncthreads();
    }

#pragma unroll
    for (int mf = 0; mf < 4; mf++) {
#pragma unroll
        for (int half_i = 0; half_i < 2; half_i++) {
            int r = row0 + wm * 64 + mf * 16 + grp + half_i * 8;
            if (r >= n) continue;
            float xa = 0.f, xb = 0.f;
            if (xr) { xa = xr[(size_t)r * 130]; xb = xr[(size_t)r * 130 + 1]; }
#pragma unroll
            for (int nf = 0; nf < 4; nf++) {
                int c = col0 + wn * 32 + nf * 8 + qid * 2;
                float v0 = acc[mf][nf][half_i * 2 + 0];
                float v1 = acc[mf][nf][half_i * 2 + 1];
                if (bias) { v0 += bias[c]; v1 += bias[c + 1]; }
                if (xr) {
                    v0 += xa * u1[c]     + xb * u2[c]     + cc[c];
                    v1 += xa * u1[c + 1] + xb * u2[c + 1] + cc[c + 1];
                }
                if (do_relu) { v0 = fmaxf(v0, 0.f); v1 = fmaxf(v1, 0.f); }
                if (OUT_HALF)
                    *(half2*)((__half*)Cv + (size_t)r * ldc + c) = __floats2half2_rn(v0, v1);
                else
                    *(float2*)((float*)Cv + (size_t)r * ldc + c) = make_float2(v0, v1);
            }
        }
    }
}

// ---------------- split 3xTF32 GEMM, 2-stage cp.async (h / fc3) ---------------
#define TS_ASZ (128 * 36)
#define TS_BSZ (32 * 72)
#define TS_SMEM ((2 * (TS_ASZ + TS_BSZ)) * 4)
__global__ void __launch_bounds__(128)
tf32s_gemm(const float* __restrict__ A, int lda,
           const float* __restrict__ W, int ldw,
           const float* __restrict__ bias,
           float* __restrict__ C, int ldc,
           int n, int K) {
    constexpr int BM = 128, BK = 32, BN = 64;
    extern __shared__ float smem[];
    float* Asf = smem;
    float* Bsf = smem + 2 * TS_ASZ;

    const int tid = threadIdx.x;
    const int warp = tid >> 5, lane = tid & 31;
    const int wm = warp >> 1;
    const int wn = warp & 1;
    const int grp = lane >> 2, qid = lane & 3;
    const int row0 = blockIdx.x * BM;
    const int col0 = blockIdx.y * BN;
    const int nk = K / BK;

    float acc[4][4][4] = {};

    auto load_tile = [&](int s, int kk) {
        float* At = Asf + s * TS_ASZ;
        float* Bt = Bsf + s * TS_BSZ;
#pragma unroll
        for (int l = 0; l < 16; l++) {
            int i = tid + l * 128;
            int r = i >> 4, c2 = (i & 15) * 2;
            int gr = row0 + r;
            bool v = gr < n;
            cp8(&At[r * 36 + c2], A + (size_t)(v ? gr : n - 1) * lda + kk + c2, v);
        }
#pragma unroll
        for (int l = 0; l < 4; l++) {
            int i = tid + l * 128;
            int r = i >> 4, c4 = (i & 15) * 4;
            cp16(&Bt[r * 72 + c4], &W[(size_t)(kk + r) * ldw + col0 + c4], true);
        }
        CP_COMMIT();
    };

    load_tile(0, 0);
    for (int t = 0; t < nk; t++) {
        if (t + 1 < nk) load_tile((t + 1) & 1, (t + 1) * BK);
        if (t + 1 < nk) CP_WAIT1(); else CP_WAIT0();
        __syncthreads();
        const float* At = Asf + (t & 1) * TS_ASZ;
        const float* Bt = Bsf + (t & 1) * TS_BSZ;
#pragma unroll
        for (int ks = 0; ks < BK / 8; ks++) {
            const int k0 = ks * 8;
            unsigned ah[4][4], al[4][4], bh[4][2], bl[4][2];
#pragma unroll
            for (int mf = 0; mf < 4; mf++) {
                int r = wm * 64 + mf * 16 + grp;
                float x0 = At[r * 36 + k0 + qid];
                float x1 = At[(r + 8) * 36 + k0 + qid];
                float x2 = At[r * 36 + k0 + qid + 4];
                float x3 = At[(r + 8) * 36 + k0 + qid + 4];
                ah[mf][0] = f2tf(x0); al[mf][0] = f2tf(x0 - __uint_as_float(ah[mf][0]));
                ah[mf][1] = f2tf(x1); al[mf][1] = f2tf(x1 - __uint_as_float(ah[mf][1]));
                ah[mf][2] = f2tf(x2); al[mf][2] = f2tf(x2 - __uint_as_float(ah[mf][2]));
                ah[mf][3] = f2tf(x3); al[mf][3] = f2tf(x3 - __uint_as_float(ah[mf][3]));
            }
#pragma unroll
            for (int nf = 0; nf < 4; nf++) {
                int c = wn * 32 + nf * 8 + grp;
                float y0 = Bt[(k0 + qid) * 72 + c];
                float y1 = Bt[(k0 + qid + 4) * 72 + c];
                bh[nf][0] = f2tf(y0); bl[nf][0] = f2tf(y0 - __uint_as_float(bh[nf][0]));
                bh[nf][1] = f2tf(y1); bl[nf][1] = f2tf(y1 - __uint_as_float(bh[nf][1]));
            }
#pragma unroll
            for (int mf = 0; mf < 4; mf++)
#pragma unroll
                for (int nf = 0; nf < 4; nf++) {
                    mma_tf32(acc[mf][nf], al[mf], bh[nf]);
                    mma_tf32(acc[mf][nf], ah[mf], bl[nf]);
                    mma_tf32(acc[mf][nf], ah[mf], bh[nf]);
                }
        }
        __syncthreads();
    }

#pragma unroll
    for (int mf = 0; mf < 4; mf++) {
#pragma unroll
        for (int half_i = 0; half_i < 2; half_i++) {
            int r = row0 + wm * 64 + mf * 16 + grp + half_i * 8;
            if (r >= n) continue;
#pragma unroll
            for (int nf = 0; nf < 4; nf++) {
                int c = col0 + wn * 32 + nf * 8 + qid * 2;
                float v0 = acc[mf][nf][half_i * 2 + 0];
                float v1 = acc[mf][nf][half_i * 2 + 1];
                if (bias) { v0 += bias[c]; v1 += bias[c + 1]; }
                *(float2*)&C[(size_t)r * ldc + c] = make_float2(v0, v1);
            }
        }
    }
}

// -----------------------------------------------------------------------------
extern "C" void kernel_launch(void* const* d_in, const int* in_sizes, int n_in,
                              void* d_out, int out_size) {
    const float* x    = (const float*)d_in[0];
    const void*  ei   = d_in[1];
    const float* w1   = (const float*)d_in[2];
    const float* b1   = (const float*)d_in[3];
    const float* w2   = (const float*)d_in[4];
    const float* b2   = (const float*)d_in[5];
    const float* gatw = (const float*)d_in[6];
    const float* asrc = (const float*)d_in[7];
    const float* adst = (const float*)d_in[8];
    const float* gatb = (const float*)d_in[9];
    const float* fc1w = (const float*)d_in[10];
    const float* fc1b = (const float*)d_in[11];
    const float* fc2w = (const float*)d_in[12];
    const float* fc2b = (const float*)d_in[13];
    const float* fc3w = (const float*)d_in[14];
    const float* fc3b = (const float*)d_in[15];
    float* out = (float*)d_out;

    void *ph, *px3h, *ph1h, *ph2, *pu1, *pu2, *pcc, *pw1t, *pw2t;
    cudaGetSymbolAddress(&ph,   g_h);
    cudaGetSymbolAddress(&px3h, g_x3h);
    cudaGetSymbolAddress(&ph1h, g_h1h);
    cudaGetSymbolAddress(&ph2,  g_h2);
    cudaGetSymbolAddress(&pu1,  g_u1);
    cudaGetSymbolAddress(&pu2,  g_u2);
    cudaGetSymbolAddress(&pcc,  g_cc);
    cudaGetSymbolAddress(&pw1t, g_w1t);
    cudaGetSymbolAddress(&pw2t, g_w2t);

    static int attr_done = 0;
    if (!attr_done) {
        cudaFuncSetAttribute(f16_gemm<1>, cudaFuncAttributeMaxDynamicSharedMemorySize, HG_SMEM);
        cudaFuncSetAttribute(f16_gemm<0>, cudaFuncAttributeMaxDynamicSharedMemorySize, HG_SMEM);
        cudaFuncSetAttribute(tf32s_gemm,  cudaFuncAttributeMaxDynamicSharedMemorySize, TS_SMEM);
        attr_done = 1;
    }

    const int GX = (NN + 127) / 128;   // 782

    detect_kernel<<<1, 256>>>((const unsigned*)ei);
    prep_kernel<<<1, 384>>>(w1, b1, w2, b2, gatb, fc1w, fc1b);
    tr_kernel<<<192, 256>>>(fc1w, fc2w);
    zero_cnt_kernel<<<(NN + 255) / 256, 256>>>();

    // CSR build
    hist_kernel<<<(EE + 255) / 256, 256>>>(ei);
    scan1_kernel<<<NSB, 256>>>();
    scan2_kernel<<<1, 256>>>();
    scan3_kernel<<<NSB, 512>>>();

    // h = x[:,2:130] @ gat_w  (split 3xTF32: fp32-accurate, feeds exp)
    tf32s_gemm<<<dim3(GX, 1), 128, TS_SMEM>>>(x + 2, 130, gatw, 64, nullptr,
                                              (float*)ph, 64, NN, 128);
    alpha_kernel<<<(NN * 32 + 255) / 256, 256>>>(asrc, adst);
    scatter_kernel<<<(EE + 255) / 256, 256>>>(ei);
    agg_kernel<<<(NN * 32 + 255) / 256, 256>>>();

    // fc1 (fp16 mma): relu( x3 @ fc1_w[128:192,:] + x0*u1 + x1*u2 + cc ) -> h1 fp16
    f16_gemm<1><<<dim3(GX, 3), 256, HG_SMEM>>>((const __half*)px3h, 64,
                                               (const __half*)pw1t, 64, nullptr,
                                               ph1h, 384, NN, 64, 1,
                                               x, (const float*)pu1, (const float*)pu2, (const float*)pcc);
    // fc2 (fp16 mma): relu( h1 @ fc2_w + fc2_b ) -> h2 fp32
    f16_gemm<0><<<dim3(GX, 1), 256, HG_SMEM>>>((const __half*)ph1h, 384,
                                               (const __half*)pw2t, 384, fc2b,
                                               ph2, 128, NN, 384, 1,
                                               nullptr, nullptr, nullptr, nullptr);
    // fc3 (split 3xTF32, final output): h2 @ fc3_w + fc3_b
    tf32s_gemm<<<dim3(GX, 1), 128, TS_SMEM>>>((const float*)ph2, 128, fc3w, 64, fc3b,
                                              out, 64, NN, 128);
}